// round 13
// baseline (speedup 1.0000x reference)
#include <cuda_runtime.h>
#include <cuda_bf16.h>
#include <cstdint>

#define NNODES 50000
#define MAXEDGES 800000
#define HID 128
#define EMB 64
#define KCLUS 10
#define KPADMAX 1024

// ---------------- scratch (device globals; no allocation allowed) ----------------
__device__ float g_xw  [NNODES * HID];
__device__ float g_h   [NNODES * HID];
__device__ float g_hw  [NNODES * EMB];
__device__ float g_zcat[NNODES * 3 * EMB];
__device__ int   g_cnt [NNODES];
__device__ int   g_off [NNODES + 1];
__device__ int   g_cur [NNODES];
__device__ int   g_scols[MAXEDGES];
__device__ float g_svals[MAXEDGES];
__device__ int   g_bsum[64];
__device__ __nv_bfloat16 g_wThi[HID * KPADMAX];
__device__ __nv_bfloat16 g_wTlo[HID * KPADMAX];

// ---------------- weight transpose + bf16 hi/lo split (small) -------------------
__global__ void __launch_bounds__(256)
convw_kernel(const float* __restrict__ w1, __nv_bfloat16* __restrict__ hiT,
             __nv_bfloat16* __restrict__ loT, int din, int Kpad)
{
    int idx = blockIdx.x * blockDim.x + threadIdx.x;
    if (idx >= HID * Kpad) return;
    int n = idx / Kpad;
    int k = idx - n * Kpad;
    float v = (k < din) ? w1[(size_t)k * HID + n] : 0.f;
    __nv_bfloat16 h = __float2bfloat16(v);
    __nv_bfloat16 l = __float2bfloat16(v - __bfloat162float(h));
    hiT[(size_t)n * KPADMAX + k] = h;
    loT[(size_t)n * KPADMAX + k] = l;
}

// =================================================================================
// GEMM1 v3: fused fp32->bf16 split + mma.sync m16n8k16, CTA tile 128x128.
// A: LDG fp32 (register prefetch) -> split hi/lo -> STS.  B: cp.async from wT.
// 8 warps: wm(2) x wn(4); warp tile 64x32. smem row stride 48B, conflict-free.
// =================================================================================
#define SMROW 48
#define OFF_AH 0
#define OFF_AL 6144
#define OFF_BH 12288
#define OFF_BL 18432
#define STAGE_BYTES 24576

static __device__ __forceinline__ uint32_t smem_u32(const void* p) {
    uint32_t a;
    asm("{ .reg .u64 t; cvta.to.shared.u64 t, %1; cvt.u32.u64 %0, t; }" : "=r"(a) : "l"(p));
    return a;
}

#define CPASYNC16(dst, src) \
    asm volatile("cp.async.ca.shared.global [%0], [%1], 16;" :: "r"(dst), "l"(src))
#define CP_COMMIT() asm volatile("cp.async.commit_group;" ::: "memory")
#define CP_WAIT0()  asm volatile("cp.async.wait_group 0;" ::: "memory")
#define CP_WAIT1()  asm volatile("cp.async.wait_group 1;" ::: "memory")

#define LDSM4(r0, r1, r2, r3, addr) \
    asm volatile("ldmatrix.sync.aligned.m8n8.x4.shared.b16 {%0,%1,%2,%3}, [%4];" \
                 : "=r"(r0), "=r"(r1), "=r"(r2), "=r"(r3) : "r"(addr))

#define MMA16816(c, a0, a1, a2, a3, b0, b1)                                   \
    asm volatile(                                                             \
        "mma.sync.aligned.m16n8k16.row.col.f32.bf16.bf16.f32 "                \
        "{%0,%1,%2,%3}, {%4,%5,%6,%7}, {%8,%9}, {%0,%1,%2,%3};"               \
        : "+f"((c)[0]), "+f"((c)[1]), "+f"((c)[2]), "+f"((c)[3])              \
        : "r"(a0), "r"(a1), "r"(a2), "r"(a3), "r"(b0), "r"(b1))

__global__ void __launch_bounds__(256)
gemm1_mma(const float* __restrict__ X,
          const __nv_bfloat16* __restrict__ BhiT, const __nv_bfloat16* __restrict__ BloT,
          float* __restrict__ C, int M, int din, int nChunk)
{
    __shared__ __align__(16) uint8_t sm[2][STAGE_BYTES];

    const int tid  = threadIdx.x;
    const int lane = tid & 31;
    const int wid  = tid >> 5;
    const int wm   = wid >> 2;          // 0..1 -> 64 rows
    const int wn   = wid & 3;           // 0..3 -> 32 cols
    const int g    = lane >> 2;
    const int t    = lane & 3;
    const int bm   = blockIdx.x * 128;

    const uint32_t smb = smem_u32(sm);

    float acc[4][4][4];
    #pragma unroll
    for (int i = 0; i < 4; i++)
        #pragma unroll
        for (int j = 0; j < 4; j++)
            #pragma unroll
            for (int r = 0; r < 4; r++) acc[i][j][r] = 0.f;

    // A mapping: thread owns row tid>>1, 8 fp32 cols at (tid&1)*8
    const int arow  = tid >> 1;
    const int ahalf = (tid & 1) * 8;
    const int aGr   = bm + arow;
    const bool aOk  = aGr < M;
    const float* aBase = X + (size_t)(aOk ? aGr : 0) * din + ahalf;

    // B mapping: thread copies 16B of hi and 16B of lo for row tid>>1, chunk (tid&1)
    const int brow = tid >> 1;
    const int bc16 = tid & 1;
    const __nv_bfloat16* bhSrc = BhiT + (size_t)brow * KPADMAX + bc16 * 8;
    const __nv_bfloat16* blSrc = BloT + (size_t)brow * KPADMAX + bc16 * 8;
    const uint32_t bhDst = smb + OFF_BH + brow * SMROW + bc16 * 16;
    const uint32_t blDst = smb + OFF_BL + brow * SMROW + bc16 * 16;

    float4 pv0, pv1;
    auto ldgA = [&](int ch) {
        const int gk = ch * 16;
        if (aOk && (gk + ahalf) < din) {
            pv0 = *(const float4*)(aBase + gk);
            pv1 = *(const float4*)(aBase + gk + 4);
        } else {
            pv0 = make_float4(0.f, 0.f, 0.f, 0.f);
            pv1 = pv0;
        }
    };
    auto stsA = [&](int stg) {
        float f[8] = {pv0.x, pv0.y, pv0.z, pv0.w, pv1.x, pv1.y, pv1.z, pv1.w};
        __nv_bfloat16 h[8], l[8];
        #pragma unroll
        for (int i = 0; i < 8; i++) {
            h[i] = __float2bfloat16(f[i]);
            l[i] = __float2bfloat16(f[i] - __bfloat162float(h[i]));
        }
        const uint32_t base = smb + stg * STAGE_BYTES + arow * SMROW + ahalf * 2;
        asm volatile("st.shared.v4.b32 [%0], {%1,%2,%3,%4};" :: "r"(base + OFF_AH),
            "r"(*(const uint32_t*)&h[0]), "r"(*(const uint32_t*)&h[2]),
            "r"(*(const uint32_t*)&h[4]), "r"(*(const uint32_t*)&h[6]) : "memory");
        asm volatile("st.shared.v4.b32 [%0], {%1,%2,%3,%4};" :: "r"(base + OFF_AL),
            "r"(*(const uint32_t*)&l[0]), "r"(*(const uint32_t*)&l[2]),
            "r"(*(const uint32_t*)&l[4]), "r"(*(const uint32_t*)&l[6]) : "memory");
    };
    auto cpB = [&](int stg, int ch) {
        const int gk = ch * 16;
        const uint32_t so = stg * STAGE_BYTES;
        CPASYNC16(bhDst + so, bhSrc + gk);
        CPASYNC16(blDst + so, blSrc + gk);
    };

    // ldmatrix lane addressing
    const int lrow = (lane < 16) ? lane : lane - 16;
    const uint32_t lcol = (lane < 16) ? 0 : 16;
    const uint32_t aAddrOff = (uint32_t)(wm * 64 + lrow) * SMROW + lcol;
    const uint32_t bAddrOff = (uint32_t)(wn * 32 + lrow) * SMROW + lcol;

    ldgA(0);
    cpB(0, 0);
    CP_COMMIT();
    stsA(0);

    for (int ch = 0; ch < nChunk; ch++) {
        const int stg = ch & 1;
        if (ch + 1 < nChunk) {
            ldgA(ch + 1);
            cpB(stg ^ 1, ch + 1);
            CP_COMMIT();
            CP_WAIT1();
        } else {
            CP_WAIT0();
        }
        __syncthreads();

        const uint32_t sb = smb + stg * STAGE_BYTES;

        uint32_t bh[8], bl[8];
        LDSM4(bh[0], bh[1], bh[2], bh[3], sb + OFF_BH + bAddrOff);
        LDSM4(bh[4], bh[5], bh[6], bh[7], sb + OFF_BH + bAddrOff + 16 * SMROW);
        LDSM4(bl[0], bl[1], bl[2], bl[3], sb + OFF_BL + bAddrOff);
        LDSM4(bl[4], bl[5], bl[6], bl[7], sb + OFF_BL + bAddrOff + 16 * SMROW);

        if (ch + 1 < nChunk) stsA(stg ^ 1);

        #pragma unroll
        for (int ma = 0; ma < 4; ma++) {
            uint32_t ah0, ah1, ah2, ah3, al0, al1, al2, al3;
            const uint32_t ao = aAddrOff + (uint32_t)(ma * 16) * SMROW;
            LDSM4(ah0, ah1, ah2, ah3, sb + OFF_AH + ao);
            LDSM4(al0, al1, al2, al3, sb + OFF_AL + ao);
            #pragma unroll
            for (int na = 0; na < 4; na++) {
                const uint32_t b0h = bh[(na >> 1) * 4 + (na & 1)];
                const uint32_t b1h = bh[(na >> 1) * 4 + (na & 1) + 2];
                const uint32_t b0l = bl[(na >> 1) * 4 + (na & 1)];
                const uint32_t b1l = bl[(na >> 1) * 4 + (na & 1) + 2];
                MMA16816(acc[ma][na], ah0, ah1, ah2, ah3, b0h, b1h);
                MMA16816(acc[ma][na], ah0, ah1, ah2, ah3, b0l, b1l);
                MMA16816(acc[ma][na], al0, al1, al2, al3, b0h, b1h);
            }
        }
        __syncthreads();
    }

    // epilogue
    #pragma unroll
    for (int ma = 0; ma < 4; ma++) {
        int r0 = bm + wm * 64 + ma * 16 + g;
        int r1 = r0 + 8;
        #pragma unroll
        for (int na = 0; na < 4; na++) {
            int cc = wn * 32 + (na & 1) * 8 + (na >> 1) * 16 + 2 * t;
            if (r0 < M)
                *(float2*)&C[(size_t)r0 * HID + cc] = make_float2(acc[ma][na][0], acc[ma][na][1]);
            if (r1 < M)
                *(float2*)&C[(size_t)r1 * HID + cc] = make_float2(acc[ma][na][2], acc[ma][na][3]);
        }
    }
}

// ---------------- tiled fp32 SGEMM (round-5 proven version) ---------------------
#define BM 128
#define BN 64
#define BK 8
#define TM 8
#define TN 4

template<bool EPI_BIAS_RELU>
__global__ void __launch_bounds__(256)
sgemm_kernel(const float* __restrict__ A, const float* __restrict__ B,
             const float* __restrict__ bias, float* __restrict__ C,
             int M, int K, int nc)
{
    __shared__ float As[BK][BM];
    __shared__ float Bs[BK][BN];

    const int tid = threadIdx.x;
    const int bm  = blockIdx.x * BM;
    const int bn  = blockIdx.y * BN;
    const int tx  = tid & 15;
    const int ty  = tid >> 4;

    float acc[TM][TN];
    #pragma unroll
    for (int i = 0; i < TM; i++)
        #pragma unroll
        for (int j = 0; j < TN; j++) acc[i][j] = 0.f;

    const int arow = tid >> 1;
    const int acol = (tid & 1) * 4;
    const int brow = tid >> 5;
    const int bcol = (tid & 31) * 2;

    const bool avalid = (bm + arow) < M;
    const float* Abase = A + (size_t)(bm + arow) * K + acol;
    const float* Bbase = B + (size_t)brow * nc + bn + bcol;

    for (int k0 = 0; k0 < K; k0 += BK) {
        float4 av = make_float4(0.f, 0.f, 0.f, 0.f);
        if (avalid) av = *(const float4*)(Abase + k0);
        As[acol + 0][arow] = av.x;
        As[acol + 1][arow] = av.y;
        As[acol + 2][arow] = av.z;
        As[acol + 3][arow] = av.w;

        float2 bv = *(const float2*)(Bbase + (size_t)k0 * nc);
        Bs[brow][bcol]     = bv.x;
        Bs[brow][bcol + 1] = bv.y;
        __syncthreads();

        #pragma unroll
        for (int kk = 0; kk < BK; kk++) {
            float4 a0 = *(const float4*)&As[kk][ty * TM];
            float4 a1 = *(const float4*)&As[kk][ty * TM + 4];
            float4 b0 = *(const float4*)&Bs[kk][tx * TN];
            float a[TM] = {a0.x, a0.y, a0.z, a0.w, a1.x, a1.y, a1.z, a1.w};
            float b[TN] = {b0.x, b0.y, b0.z, b0.w};
            #pragma unroll
            for (int i = 0; i < TM; i++)
                #pragma unroll
                for (int j = 0; j < TN; j++)
                    acc[i][j] = fmaf(a[i], b[j], acc[i][j]);
        }
        __syncthreads();
    }

    float bv[TN] = {0.f, 0.f, 0.f, 0.f};
    if (EPI_BIAS_RELU) {
        #pragma unroll
        for (int j = 0; j < TN; j++) bv[j] = bias[bn + tx * TN + j];
    }

    #pragma unroll
    for (int i = 0; i < TM; i++) {
        int r = bm + ty * TM + i;
        if (r < M) {
            float4 o;
            float v0 = acc[i][0], v1 = acc[i][1], v2 = acc[i][2], v3 = acc[i][3];
            if (EPI_BIAS_RELU) {
                v0 = fmaxf(v0 + bv[0], 0.f);
                v1 = fmaxf(v1 + bv[1], 0.f);
                v2 = fmaxf(v2 + bv[2], 0.f);
                v3 = fmaxf(v3 + bv[3], 0.f);
            }
            o.x = v0; o.y = v1; o.z = v2; o.w = v3;
            *(float4*)(C + (size_t)r * nc + bn + tx * TN) = o;
        }
    }
}

// =================================================================================
// CSR construction: count -> hierarchical scan -> scatter
// =================================================================================
__global__ void zero_kernel(int* p, int n)
{
    int i = blockIdx.x * blockDim.x + threadIdx.x;
    if (i < n) p[i] = 0;
}

__global__ void count_kernel(const int* __restrict__ rows, int* __restrict__ cnt, int E)
{
    int e = blockIdx.x * blockDim.x + threadIdx.x;
    if (e < E) atomicAdd(&cnt[rows[e]], 1);
}

__global__ void __launch_bounds__(256)
deg_reduce(const int* __restrict__ cnt, int* __restrict__ bsum, int n)
{
    __shared__ int sh[256];
    int t = threadIdx.x;
    int base = blockIdx.x * 1024 + t * 4;
    int s = 0;
    if (base + 3 < n) {
        int4 v = *(const int4*)(cnt + base);
        s = v.x + v.y + v.z + v.w;
    } else {
        for (int i = 0; i < 4; i++) if (base + i < n) s += cnt[base + i];
    }
    sh[t] = s;
    __syncthreads();
    for (int d = 128; d > 0; d >>= 1) {
        if (t < d) sh[t] += sh[t + d];
        __syncthreads();
    }
    if (t == 0) bsum[blockIdx.x] = sh[0];
}

__global__ void __launch_bounds__(256)
scan_bsums(int* bsum, int nb)
{
    __shared__ int sh[256];
    int t = threadIdx.x;
    int v = (t < nb) ? bsum[t] : 0;
    sh[t] = v;
    __syncthreads();
    for (int d = 1; d < 256; d <<= 1) {
        int u = (t >= d) ? sh[t - d] : 0;
        __syncthreads();
        sh[t] += u;
        __syncthreads();
    }
    if (t < nb) bsum[t] = sh[t] - v;
}

__global__ void __launch_bounds__(256)
scan_apply(const int* __restrict__ cnt, const int* __restrict__ bsum,
           int* __restrict__ off, int* __restrict__ cur, int n, int E)
{
    __shared__ int sh[256];
    int t = threadIdx.x;
    int base = blockIdx.x * 1024 + t * 4;
    int c[4];
    int s = 0;
    #pragma unroll
    for (int i = 0; i < 4; i++) {
        c[i] = (base + i < n) ? cnt[base + i] : 0;
        s += c[i];
    }
    sh[t] = s;
    __syncthreads();
    for (int d = 1; d < 256; d <<= 1) {
        int u = (t >= d) ? sh[t - d] : 0;
        __syncthreads();
        sh[t] += u;
        __syncthreads();
    }
    int pre = bsum[blockIdx.x] + sh[t] - s;
    #pragma unroll
    for (int i = 0; i < 4; i++) {
        if (base + i < n) {
            off[base + i] = pre;
            cur[base + i] = pre;
            pre += c[i];
        }
    }
    if (blockIdx.x == 0 && t == 0) off[n] = E;
}

__global__ void scatter_kernel(const int* __restrict__ rows, const int* __restrict__ cols,
                               const float* __restrict__ vals, int* __restrict__ cur,
                               int* __restrict__ scols, float* __restrict__ svals, int E)
{
    int e = blockIdx.x * blockDim.x + threadIdx.x;
    if (e < E) {
        int p = atomicAdd(&cur[rows[e]], 1);
        scols[p] = cols[e];
        svals[p] = vals[e];
    }
}

// ---------------- row-per-warp SpMM, vectorized + unroll-4 -----------------------
template<int NC, bool RELU>
__global__ void __launch_bounds__(256)
spmm_kernel(const int* __restrict__ off, const int* __restrict__ scols,
            const float* __restrict__ svals, const float* __restrict__ dense,
            const float* __restrict__ bias,
            float* __restrict__ out, int ldo,
            float* __restrict__ out2, int ldo2, int n)
{
    const int warp = (blockIdx.x * blockDim.x + threadIdx.x) >> 5;
    const int lane = threadIdx.x & 31;
    if (warp >= n) return;

    const int s = off[warp];
    const int e = off[warp + 1];
    constexpr int V = NC / 32;
    const int c = lane * V;

    float acc[V];
    #pragma unroll
    for (int i = 0; i < V; i++) acc[i] = 0.f;

    int j = s;
    for (; j + 3 < e; j += 4) {
        int   ci[4];
        float vi[4];
        #pragma unroll
        for (int u = 0; u < 4; u++) { ci[u] = scols[j + u]; vi[u] = svals[j + u]; }
        if (V == 4) {
            float4 x[4];
            #pragma unroll
            for (int u = 0; u < 4; u++)
                x[u] = *(const float4*)(dense + (size_t)ci[u] * NC + c);
            #pragma unroll
            for (int u = 0; u < 4; u++) {
                acc[0] = fmaf(vi[u], x[u].x, acc[0]); acc[1] = fmaf(vi[u], x[u].y, acc[1]);
                acc[2] = fmaf(vi[u], x[u].z, acc[2]); acc[3] = fmaf(vi[u], x[u].w, acc[3]);
            }
        } else {
            float2 x[4];
            #pragma unroll
            for (int u = 0; u < 4; u++)
                x[u] = *(const float2*)(dense + (size_t)ci[u] * NC + c);
            #pragma unroll
            for (int u = 0; u < 4; u++) {
                acc[0] = fmaf(vi[u], x[u].x, acc[0]); acc[1] = fmaf(vi[u], x[u].y, acc[1]);
            }
        }
    }
    for (; j < e; j++) {
        const int   cc = scols[j];
        const float v  = svals[j];
        const float* dr = dense + (size_t)cc * NC + c;
        if (V == 4) {
            float4 x = *(const float4*)dr;
            acc[0] = fmaf(v, x.x, acc[0]); acc[1] = fmaf(v, x.y, acc[1]);
            acc[2] = fmaf(v, x.z, acc[2]); acc[3] = fmaf(v, x.w, acc[3]);
        } else {
            float2 x = *(const float2*)dr;
            acc[0] = fmaf(v, x.x, acc[0]); acc[1] = fmaf(v, x.y, acc[1]);
        }
    }

    float r[V];
    #pragma unroll
    for (int i = 0; i < V; i++) {
        r[i] = acc[i] + bias[c + i];
        if (RELU) r[i] = fmaxf(r[i], 0.f);
    }
    if (V == 4) {
        *(float4*)(out + (size_t)warp * ldo + c) = make_float4(r[0], r[1], r[2], r[3]);
        if (out2)
            *(float4*)(out2 + (size_t)warp * ldo2 + c) = make_float4(r[0], r[1], r[2], r[3]);
    } else {
        *(float2*)(out + (size_t)warp * ldo + c) = make_float2(r[0], r[1]);
        if (out2)
            *(float2*)(out2 + (size_t)warp * ldo2 + c) = make_float2(r[0], r[1]);
    }
}

// ---------------- DEC soft assignment q ----------------
__global__ void __launch_bounds__(256)
q_kernel(const float* __restrict__ zf, const float* __restrict__ cluster,
         float* __restrict__ q, int n)
{
    __shared__ float cs[KCLUS * EMB];
    for (int i = threadIdx.x; i < KCLUS * EMB; i += blockDim.x) cs[i] = cluster[i];
    __syncthreads();

    int nid = blockIdx.x * blockDim.x + threadIdx.x;
    if (nid >= n) return;

    float z[EMB];
    const float* zr = zf + (size_t)nid * EMB;
    #pragma unroll
    for (int i = 0; i < EMB; i++) z[i] = zr[i];

    float qq[KCLUS];
    float s = 0.f;
    #pragma unroll
    for (int k = 0; k < KCLUS; k++) {
        float d = 0.f;
        #pragma unroll
        for (int i = 0; i < EMB; i++) {
            float diff = z[i] - cs[k * EMB + i];
            d = fmaf(diff, diff, d);
        }
        qq[k] = 1.f / (1.f + d);
        s += qq[k];
    }
    float inv = 1.f / s;
    #pragma unroll
    for (int k = 0; k < KCLUS; k++)
        q[(size_t)nid * KCLUS + k] = qq[k] * inv;
}

// ---------------- host launcher ----------------
extern "C" void kernel_launch(void* const* d_in, const int* in_sizes, int n_in,
                              void* d_out, int out_size)
{
    float *xw, *h, *hw, *zcat, *svals;
    int *cnt, *off, *cur, *scols, *bsum;
    void *wThi, *wTlo;
    cudaGetSymbolAddress((void**)&xw,    g_xw);
    cudaGetSymbolAddress((void**)&h,     g_h);
    cudaGetSymbolAddress((void**)&hw,    g_hw);
    cudaGetSymbolAddress((void**)&zcat,  g_zcat);
    cudaGetSymbolAddress((void**)&cnt,   g_cnt);
    cudaGetSymbolAddress((void**)&off,   g_off);
    cudaGetSymbolAddress((void**)&cur,   g_cur);
    cudaGetSymbolAddress((void**)&scols, g_scols);
    cudaGetSymbolAddress((void**)&svals, g_svals);
    cudaGetSymbolAddress((void**)&bsum,  g_bsum);
    cudaGetSymbolAddress(&wThi, g_wThi);
    cudaGetSymbolAddress(&wTlo, g_wTlo);

    float* out = (float*)d_out;
    const int N = NNODES;

    int IX[3], IR[3], IC[3], IV[3], IW1[3], IB1[3], IW2[3], IB2[3], IFW, IFB, ICL;
    bool dictOrder = (n_in >= 3) && (in_sizes[1] == in_sizes[2]) && (in_sizes[1] < in_sizes[0]);
    if (dictOrder) {
        for (int v = 0; v < 3; v++) {
            IX[v] = 8 * v + 0; IR[v] = 8 * v + 1; IC[v] = 8 * v + 2; IV[v] = 8 * v + 3;
            IW1[v] = 8 * v + 4; IB1[v] = 8 * v + 5; IW2[v] = 8 * v + 6; IB2[v] = 8 * v + 7;
        }
        IFW = 24; IFB = 25; ICL = 26;
    } else {
        for (int v = 0; v < 3; v++) {
            IX[v] = v;
            IR[v] = 3 + 3 * v; IC[v] = 4 + 3 * v; IV[v] = 5 + 3 * v;
            IW1[v] = 12 + 4 * v; IB1[v] = 13 + 4 * v; IW2[v] = 14 + 4 * v; IB2[v] = 15 + 4 * v;
        }
        IFW = 24; IFB = 25; ICL = 26;
    }

    for (int v = 0; v < 3; v++) {
        const float* x    = (const float*)d_in[IX[v]];
        const int*   rows = (const int*)  d_in[IR[v]];
        const int*   cols = (const int*)  d_in[IC[v]];
        const float* vals = (const float*)d_in[IV[v]];
        const float* w1   = (const float*)d_in[IW1[v]];
        const float* b1   = (const float*)d_in[IB1[v]];
        const float* w2   = (const float*)d_in[IW2[v]];
        const float* b2   = (const float*)d_in[IB2[v]];
        const int din = in_sizes[IX[v]] / N;
        const int E   = in_sizes[IR[v]];
        const int nb  = (N + 1023) / 1024;
        const int Kpad   = ((din + 63) / 64) * 64;
        const int nChunk = (din + 15) / 16;

        // GEMM1 (fused conversion + tensor mma.sync)
        {
            int wt = HID * Kpad;
            convw_kernel<<<(wt + 255) / 256, 256>>>(w1, (__nv_bfloat16*)wThi,
                                                    (__nv_bfloat16*)wTlo, din, Kpad);
            gemm1_mma<<<(N + 127) / 128, 256>>>(x, (const __nv_bfloat16*)wThi,
                                                (const __nv_bfloat16*)wTlo, xw, N, din, nChunk);
        }
        // CSR build
        zero_kernel<<<(N + 255) / 256, 256>>>(cnt, N);
        count_kernel<<<(E + 255) / 256, 256>>>(rows, cnt, E);
        deg_reduce<<<nb, 256>>>(cnt, bsum, N);
        scan_bsums<<<1, 256>>>(bsum, nb);
        scan_apply<<<nb, 256>>>(cnt, bsum, off, cur, N, E);
        scatter_kernel<<<(E + 255) / 256, 256>>>(rows, cols, vals, cur, scols, svals, E);
        // SpMM1 + bias + relu -> h [N, HID]
        spmm_kernel<HID, true><<<(N + 7) / 8, 256>>>(off, scols, svals, xw, b1,
                                                     h, HID, nullptr, 0, N);
        // GEMM2: hw = h @ w2  [N, EMB]
        {
            dim3 grid((N + BM - 1) / BM, EMB / BN);
            sgemm_kernel<false><<<grid, 256>>>(h, w2, nullptr, hw, N, HID, EMB);
        }
        // SpMM2 + bias -> z_v, dual-write
        spmm_kernel<EMB, false><<<(N + 7) / 8, 256>>>(off, scols, svals, hw, b2,
                                                      out + (size_t)v * N * EMB, EMB,
                                                      zcat + (size_t)v * EMB, 3 * EMB, N);
    }

    const float* fw = (const float*)d_in[IFW];
    const float* fb = (const float*)d_in[IFB];
    const float* cl = (const float*)d_in[ICL];
    float* zf = out + (size_t)3 * N * EMB;
    float* qp = out + (size_t)4 * N * EMB;

    {
        dim3 grid((N + BM - 1) / BM, EMB / BN);
        sgemm_kernel<true><<<grid, 256>>>(zcat, fw, fb, zf, N, 3 * EMB, EMB);
    }
    q_kernel<<<(N + 255) / 256, 256>>>(zf, cl, qp, N);
}

// round 15
// speedup vs baseline: 1.1429x; 1.1429x over previous
#include <cuda_runtime.h>
#include <cuda_bf16.h>
#include <cstdint>

#define NNODES 50000
#define MAXEDGES 800000
#define HID 128
#define EMB 64
#define KCLUS 10
#define KPADMAX 1024

// ---------------- scratch (device globals; no allocation allowed) ----------------
__device__ float g_xw  [NNODES * HID];
__device__ float g_h   [NNODES * HID];
__device__ float g_hw  [NNODES * EMB];
__device__ float g_zcat[NNODES * 3 * EMB];
__device__ int   g_cnt [NNODES];
__device__ int   g_off [NNODES + 1];
__device__ int   g_cur [NNODES];
__device__ int   g_scols[MAXEDGES];
__device__ float g_svals[MAXEDGES];
__device__ int   g_bsum[64];
__device__ __nv_bfloat16 g_xhi [NNODES * KPADMAX];
__device__ __nv_bfloat16 g_xlo [NNODES * KPADMAX];
__device__ __nv_bfloat16 g_wThi[HID * KPADMAX];
__device__ __nv_bfloat16 g_wTlo[HID * KPADMAX];

// =================================================================================
// fp32 -> bf16 hi/lo split conversion
// =================================================================================
__global__ void __launch_bounds__(256)
convx_kernel(const float* __restrict__ x, __nv_bfloat16* __restrict__ hi,
             __nv_bfloat16* __restrict__ lo, int Mrows, int din, int Kpad)
{
    int idx = blockIdx.x * blockDim.x + threadIdx.x;
    int half = Kpad >> 1;
    if (idx >= Mrows * half) return;
    int row = idx / half;
    int c   = (idx - row * half) * 2;

    float v0 = (c     < din) ? x[(size_t)row * din + c]     : 0.f;
    float v1 = (c + 1 < din) ? x[(size_t)row * din + c + 1] : 0.f;
    __nv_bfloat16 h0 = __float2bfloat16(v0);
    __nv_bfloat16 h1 = __float2bfloat16(v1);
    __nv_bfloat16 l0 = __float2bfloat16(v0 - __bfloat162float(h0));
    __nv_bfloat16 l1 = __float2bfloat16(v1 - __bfloat162float(h1));
    size_t o = (size_t)row * KPADMAX + c;
    *(__nv_bfloat162*)(hi + o) = __nv_bfloat162(h0, h1);
    *(__nv_bfloat162*)(lo + o) = __nv_bfloat162(l0, l1);
}

__global__ void __launch_bounds__(256)
convw_kernel(const float* __restrict__ w1, __nv_bfloat16* __restrict__ hiT,
             __nv_bfloat16* __restrict__ loT, int din, int Kpad)
{
    int idx = blockIdx.x * blockDim.x + threadIdx.x;
    if (idx >= HID * Kpad) return;
    int n = idx / Kpad;
    int k = idx - n * Kpad;
    float v = (k < din) ? w1[(size_t)k * HID + n] : 0.f;
    __nv_bfloat16 h = __float2bfloat16(v);
    __nv_bfloat16 l = __float2bfloat16(v - __bfloat162float(h));
    hiT[(size_t)n * KPADMAX + k] = h;
    loT[(size_t)n * KPADMAX + k] = l;
}

// =================================================================================
// GEMM1 (R12 proven): mma.sync m16n8k16 bf16 split hi/lo, ldmatrix fragments,
// cp.async 2-stage pipeline, K-chunk 16. CTA tile 128x64; 8 warps wm(2) x wn(4).
// =================================================================================
#define SMROW 48
#define OFF_AH 0
#define OFF_AL 6144
#define OFF_BH 12288
#define OFF_BL 15360
#define STAGE_BYTES 18432

static __device__ __forceinline__ uint32_t smem_u32(const void* p) {
    uint32_t a;
    asm("{ .reg .u64 t; cvta.to.shared.u64 t, %1; cvt.u32.u64 %0, t; }" : "=r"(a) : "l"(p));
    return a;
}

#define CPASYNC16(dst, src, sz) \
    asm volatile("cp.async.ca.shared.global [%0], [%1], 16, %2;" \
                 :: "r"(dst), "l"(src), "r"(sz))
#define CP_COMMIT() asm volatile("cp.async.commit_group;" ::: "memory")
#define CP_WAIT0()  asm volatile("cp.async.wait_group 0;" ::: "memory")
#define CP_WAIT1()  asm volatile("cp.async.wait_group 1;" ::: "memory")

#define LDSM4(r0, r1, r2, r3, addr) \
    asm volatile("ldmatrix.sync.aligned.m8n8.x4.shared.b16 {%0,%1,%2,%3}, [%4];" \
                 : "=r"(r0), "=r"(r1), "=r"(r2), "=r"(r3) : "r"(addr))

#define MMA16816(c, a0, a1, a2, a3, b0, b1)                                   \
    asm volatile(                                                             \
        "mma.sync.aligned.m16n8k16.row.col.f32.bf16.bf16.f32 "                \
        "{%0,%1,%2,%3}, {%4,%5,%6,%7}, {%8,%9}, {%0,%1,%2,%3};"               \
        : "+f"((c)[0]), "+f"((c)[1]), "+f"((c)[2]), "+f"((c)[3])              \
        : "r"(a0), "r"(a1), "r"(a2), "r"(a3), "r"(b0), "r"(b1))

__global__ void __launch_bounds__(256)
gemm1_mma(const __nv_bfloat16* __restrict__ Ahi, const __nv_bfloat16* __restrict__ Alo,
          const __nv_bfloat16* __restrict__ Bhi, const __nv_bfloat16* __restrict__ Blo,
          float* __restrict__ C, int M, int nChunk)
{
    __shared__ __align__(16) uint8_t sm[2][STAGE_BYTES];

    const int tid  = threadIdx.x;
    const int lane = tid & 31;
    const int wid  = tid >> 5;
    const int wm   = wid >> 2;
    const int wn   = wid & 3;
    const int g    = lane >> 2;
    const int t    = lane & 3;
    const int bm   = blockIdx.x * 128;
    const int bn   = blockIdx.y * 64;

    const uint32_t smb = smem_u32(sm);

    float acc[4][2][4];
    #pragma unroll
    for (int i = 0; i < 4; i++)
        #pragma unroll
        for (int j = 0; j < 2; j++)
            #pragma unroll
            for (int r = 0; r < 4; r++) acc[i][j][r] = 0.f;

    const int arow = tid >> 1;
    const int ac16 = tid & 1;
    const int bi   = tid & 127;
    const int brow = bi >> 1;
    const int bc16 = bi & 1;
    const bool doBlo = tid >= 128;
    const __nv_bfloat16* BsrcBase = doBlo ? Blo : Bhi;
    const uint32_t bDstOff = doBlo ? OFF_BL : OFF_BH;

    const int aGr    = bm + arow;
    const bool aOk   = aGr < M;
    const uint32_t aSz = aOk ? 16u : 0u;
    const size_t aRowOff = (size_t)(aOk ? aGr : 0) * KPADMAX + ac16 * 8;
    const size_t bRowOff = (size_t)(bn + brow) * KPADMAX + bc16 * 8;

    auto copyStage = [&](int stg, int ch) {
        const uint32_t sb = smb + stg * STAGE_BYTES;
        const int gk = ch * 16;
        CPASYNC16(sb + OFF_AH + arow * SMROW + ac16 * 16, Ahi + aRowOff + gk, aSz);
        CPASYNC16(sb + OFF_AL + arow * SMROW + ac16 * 16, Alo + aRowOff + gk, aSz);
        CPASYNC16(sb + bDstOff + brow * SMROW + bc16 * 16, BsrcBase + bRowOff + gk, 16u);
    };

    const int lrow = (lane < 16) ? lane : lane - 16;
    const uint32_t lcol = (lane < 16) ? 0 : 16;
    const uint32_t bAddrOff = (uint32_t)(wn * 16 + lrow) * SMROW + lcol;
    const uint32_t aAddrOff = (uint32_t)(wm * 64 + lrow) * SMROW + lcol;

    copyStage(0, 0);
    CP_COMMIT();

    for (int ch = 0; ch < nChunk; ch++) {
        if (ch + 1 < nChunk) {
            copyStage((ch + 1) & 1, ch + 1);
            CP_COMMIT();
            CP_WAIT1();
        } else {
            CP_WAIT0();
        }
        __syncthreads();

        const uint32_t sb = smb + (ch & 1) * STAGE_BYTES;

        uint32_t bh0, bh1, bh2, bh3, bl0, bl1, bl2, bl3;
        LDSM4(bh0, bh1, bh2, bh3, sb + OFF_BH + bAddrOff);
        LDSM4(bl0, bl1, bl2, bl3, sb + OFF_BL + bAddrOff);

        #pragma unroll
        for (int ma = 0; ma < 4; ma++) {
            uint32_t ah0, ah1, ah2, ah3, al0, al1, al2, al3;
            const uint32_t ao = aAddrOff + (uint32_t)(ma * 16) * SMROW;
            LDSM4(ah0, ah1, ah2, ah3, sb + OFF_AH + ao);
            LDSM4(al0, al1, al2, al3, sb + OFF_AL + ao);
            MMA16816(acc[ma][0], ah0, ah1, ah2, ah3, bh0, bh2);
            MMA16816(acc[ma][0], ah0, ah1, ah2, ah3, bl0, bl2);
            MMA16816(acc[ma][0], al0, al1, al2, al3, bh0, bh2);
            MMA16816(acc[ma][1], ah0, ah1, ah2, ah3, bh1, bh3);
            MMA16816(acc[ma][1], ah0, ah1, ah2, ah3, bl1, bl3);
            MMA16816(acc[ma][1], al0, al1, al2, al3, bh1, bh3);
        }
        __syncthreads();
    }

    #pragma unroll
    for (int ma = 0; ma < 4; ma++) {
        int r0 = bm + wm * 64 + ma * 16 + g;
        int r1 = r0 + 8;
        #pragma unroll
        for (int na = 0; na < 2; na++) {
            int cc = bn + wn * 16 + na * 8 + 2 * t;
            if (r0 < M)
                *(float2*)&C[(size_t)r0 * HID + cc] = make_float2(acc[ma][na][0], acc[ma][na][1]);
            if (r1 < M)
                *(float2*)&C[(size_t)r1 * HID + cc] = make_float2(acc[ma][na][2], acc[ma][na][3]);
        }
    }
}

// ---------------- tiled fp32 SGEMM (round-5 proven version) ---------------------
#define BM 128
#define BN 64
#define BK 8
#define TM 8
#define TN 4

template<bool EPI_BIAS_RELU>
__global__ void __launch_bounds__(256)
sgemm_kernel(const float* __restrict__ A, const float* __restrict__ B,
             const float* __restrict__ bias, float* __restrict__ C,
             int M, int K, int nc)
{
    __shared__ float As[BK][BM];
    __shared__ float Bs[BK][BN];

    const int tid = threadIdx.x;
    const int bm  = blockIdx.x * BM;
    const int bn  = blockIdx.y * BN;
    const int tx  = tid & 15;
    const int ty  = tid >> 4;

    float acc[TM][TN];
    #pragma unroll
    for (int i = 0; i < TM; i++)
        #pragma unroll
        for (int j = 0; j < TN; j++) acc[i][j] = 0.f;

    const int arow = tid >> 1;
    const int acol = (tid & 1) * 4;
    const int brow = tid >> 5;
    const int bcol = (tid & 31) * 2;

    const bool avalid = (bm + arow) < M;
    const float* Abase = A + (size_t)(bm + arow) * K + acol;
    const float* Bbase = B + (size_t)brow * nc + bn + bcol;

    for (int k0 = 0; k0 < K; k0 += BK) {
        float4 av = make_float4(0.f, 0.f, 0.f, 0.f);
        if (avalid) av = *(const float4*)(Abase + k0);
        As[acol + 0][arow] = av.x;
        As[acol + 1][arow] = av.y;
        As[acol + 2][arow] = av.z;
        As[acol + 3][arow] = av.w;

        float2 bv = *(const float2*)(Bbase + (size_t)k0 * nc);
        Bs[brow][bcol]     = bv.x;
        Bs[brow][bcol + 1] = bv.y;
        __syncthreads();

        #pragma unroll
        for (int kk = 0; kk < BK; kk++) {
            float4 a0 = *(const float4*)&As[kk][ty * TM];
            float4 a1 = *(const float4*)&As[kk][ty * TM + 4];
            float4 b0 = *(const float4*)&Bs[kk][tx * TN];
            float a[TM] = {a0.x, a0.y, a0.z, a0.w, a1.x, a1.y, a1.z, a1.w};
            float b[TN] = {b0.x, b0.y, b0.z, b0.w};
            #pragma unroll
            for (int i = 0; i < TM; i++)
                #pragma unroll
                for (int j = 0; j < TN; j++)
                    acc[i][j] = fmaf(a[i], b[j], acc[i][j]);
        }
        __syncthreads();
    }

    float bv[TN] = {0.f, 0.f, 0.f, 0.f};
    if (EPI_BIAS_RELU) {
        #pragma unroll
        for (int j = 0; j < TN; j++) bv[j] = bias[bn + tx * TN + j];
    }

    #pragma unroll
    for (int i = 0; i < TM; i++) {
        int r = bm + ty * TM + i;
        if (r < M) {
            float4 o;
            float v0 = acc[i][0], v1 = acc[i][1], v2 = acc[i][2], v3 = acc[i][3];
            if (EPI_BIAS_RELU) {
                v0 = fmaxf(v0 + bv[0], 0.f);
                v1 = fmaxf(v1 + bv[1], 0.f);
                v2 = fmaxf(v2 + bv[2], 0.f);
                v3 = fmaxf(v3 + bv[3], 0.f);
            }
            o.x = v0; o.y = v1; o.z = v2; o.w = v3;
            *(float4*)(C + (size_t)r * nc + bn + tx * TN) = o;
        }
    }
}

// =================================================================================
// CSR construction: count -> hierarchical scan -> scatter
// =================================================================================
__global__ void zero_kernel(int* p, int n)
{
    int i = blockIdx.x * blockDim.x + threadIdx.x;
    if (i < n) p[i] = 0;
}

__global__ void count_kernel(const int* __restrict__ rows, int* __restrict__ cnt, int E)
{
    int e = blockIdx.x * blockDim.x + threadIdx.x;
    if (e < E) atomicAdd(&cnt[rows[e]], 1);
}

__global__ void __launch_bounds__(256)
deg_reduce(const int* __restrict__ cnt, int* __restrict__ bsum, int n)
{
    __shared__ int sh[256];
    int t = threadIdx.x;
    int base = blockIdx.x * 1024 + t * 4;
    int s = 0;
    if (base + 3 < n) {
        int4 v = *(const int4*)(cnt + base);
        s = v.x + v.y + v.z + v.w;
    } else {
        for (int i = 0; i < 4; i++) if (base + i < n) s += cnt[base + i];
    }
    sh[t] = s;
    __syncthreads();
    for (int d = 128; d > 0; d >>= 1) {
        if (t < d) sh[t] += sh[t + d];
        __syncthreads();
    }
    if (t == 0) bsum[blockIdx.x] = sh[0];
}

__global__ void __launch_bounds__(256)
scan_bsums(int* bsum, int nb)
{
    __shared__ int sh[256];
    int t = threadIdx.x;
    int v = (t < nb) ? bsum[t] : 0;
    sh[t] = v;
    __syncthreads();
    for (int d = 1; d < 256; d <<= 1) {
        int u = (t >= d) ? sh[t - d] : 0;
        __syncthreads();
        sh[t] += u;
        __syncthreads();
    }
    if (t < nb) bsum[t] = sh[t] - v;
}

__global__ void __launch_bounds__(256)
scan_apply(const int* __restrict__ cnt, const int* __restrict__ bsum,
           int* __restrict__ off, int* __restrict__ cur, int n, int E)
{
    __shared__ int sh[256];
    int t = threadIdx.x;
    int base = blockIdx.x * 1024 + t * 4;
    int c[4];
    int s = 0;
    #pragma unroll
    for (int i = 0; i < 4; i++) {
        c[i] = (base + i < n) ? cnt[base + i] : 0;
        s += c[i];
    }
    sh[t] = s;
    __syncthreads();
    for (int d = 1; d < 256; d <<= 1) {
        int u = (t >= d) ? sh[t - d] : 0;
        __syncthreads();
        sh[t] += u;
        __syncthreads();
    }
    int pre = bsum[blockIdx.x] + sh[t] - s;
    #pragma unroll
    for (int i = 0; i < 4; i++) {
        if (base + i < n) {
            off[base + i] = pre;
            cur[base + i] = pre;
            pre += c[i];
        }
    }
    if (blockIdx.x == 0 && t == 0) off[n] = E;
}

__global__ void scatter_kernel(const int* __restrict__ rows, const int* __restrict__ cols,
                               const float* __restrict__ vals, int* __restrict__ cur,
                               int* __restrict__ scols, float* __restrict__ svals, int E)
{
    int e = blockIdx.x * blockDim.x + threadIdx.x;
    if (e < E) {
        int p = atomicAdd(&cur[rows[e]], 1);
        scols[p] = cols[e];
        svals[p] = vals[e];
    }
}

// ---------------- row-per-warp SpMM, vectorized + unroll-4 -----------------------
template<int NC, bool RELU>
__global__ void __launch_bounds__(256)
spmm_kernel(const int* __restrict__ off, const int* __restrict__ scols,
            const float* __restrict__ svals, const float* __restrict__ dense,
            const float* __restrict__ bias,
            float* __restrict__ out, int ldo,
            float* __restrict__ out2, int ldo2, int n)
{
    const int warp = (blockIdx.x * blockDim.x + threadIdx.x) >> 5;
    const int lane = threadIdx.x & 31;
    if (warp >= n) return;

    const int s = off[warp];
    const int e = off[warp + 1];
    constexpr int V = NC / 32;
    const int c = lane * V;

    float acc[V];
    #pragma unroll
    for (int i = 0; i < V; i++) acc[i] = 0.f;

    int j = s;
    for (; j + 3 < e; j += 4) {
        int   ci[4];
        float vi[4];
        #pragma unroll
        for (int u = 0; u < 4; u++) { ci[u] = scols[j + u]; vi[u] = svals[j + u]; }
        if (V == 4) {
            float4 x[4];
            #pragma unroll
            for (int u = 0; u < 4; u++)
                x[u] = *(const float4*)(dense + (size_t)ci[u] * NC + c);
            #pragma unroll
            for (int u = 0; u < 4; u++) {
                acc[0] = fmaf(vi[u], x[u].x, acc[0]); acc[1] = fmaf(vi[u], x[u].y, acc[1]);
                acc[2] = fmaf(vi[u], x[u].z, acc[2]); acc[3] = fmaf(vi[u], x[u].w, acc[3]);
            }
        } else {
            float2 x[4];
            #pragma unroll
            for (int u = 0; u < 4; u++)
                x[u] = *(const float2*)(dense + (size_t)ci[u] * NC + c);
            #pragma unroll
            for (int u = 0; u < 4; u++) {
                acc[0] = fmaf(vi[u], x[u].x, acc[0]); acc[1] = fmaf(vi[u], x[u].y, acc[1]);
            }
        }
    }
    for (; j < e; j++) {
        const int   cc = scols[j];
        const float v  = svals[j];
        const float* dr = dense + (size_t)cc * NC + c;
        if (V == 4) {
            float4 x = *(const float4*)dr;
            acc[0] = fmaf(v, x.x, acc[0]); acc[1] = fmaf(v, x.y, acc[1]);
            acc[2] = fmaf(v, x.z, acc[2]); acc[3] = fmaf(v, x.w, acc[3]);
        } else {
            float2 x = *(const float2*)dr;
            acc[0] = fmaf(v, x.x, acc[0]); acc[1] = fmaf(v, x.y, acc[1]);
        }
    }

    float r[V];
    #pragma unroll
    for (int i = 0; i < V; i++) {
        r[i] = acc[i] + bias[c + i];
        if (RELU) r[i] = fmaxf(r[i], 0.f);
    }
    if (V == 4) {
        *(float4*)(out + (size_t)warp * ldo + c) = make_float4(r[0], r[1], r[2], r[3]);
        if (out2)
            *(float4*)(out2 + (size_t)warp * ldo2 + c) = make_float4(r[0], r[1], r[2], r[3]);
    } else {
        *(float2*)(out + (size_t)warp * ldo + c) = make_float2(r[0], r[1]);
        if (out2)
            *(float2*)(out2 + (size_t)warp * ldo2 + c) = make_float2(r[0], r[1]);
    }
}

// ---------------- DEC soft assignment q ----------------
__global__ void __launch_bounds__(256)
q_kernel(const float* __restrict__ zf, const float* __restrict__ cluster,
         float* __restrict__ q, int n)
{
    __shared__ float cs[KCLUS * EMB];
    for (int i = threadIdx.x; i < KCLUS * EMB; i += blockDim.x) cs[i] = cluster[i];
    __syncthreads();

    int nid = blockIdx.x * blockDim.x + threadIdx.x;
    if (nid >= n) return;

    float z[EMB];
    const float* zr = zf + (size_t)nid * EMB;
    #pragma unroll
    for (int i = 0; i < EMB; i++) z[i] = zr[i];

    float qq[KCLUS];
    float s = 0.f;
    #pragma unroll
    for (int k = 0; k < KCLUS; k++) {
        float d = 0.f;
        #pragma unroll
        for (int i = 0; i < EMB; i++) {
            float diff = z[i] - cs[k * EMB + i];
            d = fmaf(diff, diff, d);
        }
        qq[k] = 1.f / (1.f + d);
        s += qq[k];
    }
    float inv = 1.f / s;
    #pragma unroll
    for (int k = 0; k < KCLUS; k++)
        q[(size_t)nid * KCLUS + k] = qq[k] * inv;
}

// ---------------- host launcher ----------------
extern "C" void kernel_launch(void* const* d_in, const int* in_sizes, int n_in,
                              void* d_out, int out_size)
{
    float *xw, *h, *hw, *zcat, *svals;
    int *cnt, *off, *cur, *scols, *bsum;
    void *xhi, *xlo, *wThi, *wTlo;
    cudaGetSymbolAddress((void**)&xw,    g_xw);
    cudaGetSymbolAddress((void**)&h,     g_h);
    cudaGetSymbolAddress((void**)&hw,    g_hw);
    cudaGetSymbolAddress((void**)&zcat,  g_zcat);
    cudaGetSymbolAddress((void**)&cnt,   g_cnt);
    cudaGetSymbolAddress((void**)&off,   g_off);
    cudaGetSymbolAddress((void**)&cur,   g_cur);
    cudaGetSymbolAddress((void**)&scols, g_scols);
    cudaGetSymbolAddress((void**)&svals, g_svals);
    cudaGetSymbolAddress((void**)&bsum,  g_bsum);
    cudaGetSymbolAddress(&xhi,  g_xhi);
    cudaGetSymbolAddress(&xlo,  g_xlo);
    cudaGetSymbolAddress(&wThi, g_wThi);
    cudaGetSymbolAddress(&wTlo, g_wTlo);

    float* out = (float*)d_out;
    const int N = NNODES;

    int IX[3], IR[3], IC[3], IV[3], IW1[3], IB1[3], IW2[3], IB2[3], IFW, IFB, ICL;
    bool dictOrder = (n_in >= 3) && (in_sizes[1] == in_sizes[2]) && (in_sizes[1] < in_sizes[0]);
    if (dictOrder) {
        for (int v = 0; v < 3; v++) {
            IX[v] = 8 * v + 0; IR[v] = 8 * v + 1; IC[v] = 8 * v + 2; IV[v] = 8 * v + 3;
            IW1[v] = 8 * v + 4; IB1[v] = 8 * v + 5; IW2[v] = 8 * v + 6; IB2[v] = 8 * v + 7;
        }
        IFW = 24; IFB = 25; ICL = 26;
    } else {
        for (int v = 0; v < 3; v++) {
            IX[v] = v;
            IR[v] = 3 + 3 * v; IC[v] = 4 + 3 * v; IV[v] = 5 + 3 * v;
            IW1[v] = 12 + 4 * v; IB1[v] = 13 + 4 * v; IW2[v] = 14 + 4 * v; IB2[v] = 15 + 4 * v;
        }
        IFW = 24; IFB = 25; ICL = 26;
    }

    for (int v = 0; v < 3; v++) {
        const float* x    = (const float*)d_in[IX[v]];
        const int*   rows = (const int*)  d_in[IR[v]];
        const int*   cols = (const int*)  d_in[IC[v]];
        const float* vals = (const float*)d_in[IV[v]];
        const float* w1   = (const float*)d_in[IW1[v]];
        const float* b1   = (const float*)d_in[IB1[v]];
        const float* w2   = (const float*)d_in[IW2[v]];
        const float* b2   = (const float*)d_in[IB2[v]];
        const int din = in_sizes[IX[v]] / N;
        const int E   = in_sizes[IR[v]];
        const int nb  = (N + 1023) / 1024;
        const int Kpad   = ((din + 63) / 64) * 64;
        const int nChunk = Kpad / 16;

        // GEMM1 (tensor via mma.sync): split into bf16 hi/lo, ldmatrix + cp.async
        {
            int total = N * (Kpad / 2);
            convx_kernel<<<(total + 255) / 256, 256>>>(x, (__nv_bfloat16*)xhi,
                                                       (__nv_bfloat16*)xlo, N, din, Kpad);
            int wt = HID * Kpad;
            convw_kernel<<<(wt + 255) / 256, 256>>>(w1, (__nv_bfloat16*)wThi,
                                                    (__nv_bfloat16*)wTlo, din, Kpad);
            dim3 grid((N + 127) / 128, HID / 64);
            gemm1_mma<<<grid, 256>>>((const __nv_bfloat16*)xhi, (const __nv_bfloat16*)xlo,
                                     (const __nv_bfloat16*)wThi, (const __nv_bfloat16*)wTlo,
                                     xw, N, nChunk);
        }
        // CSR build
        zero_kernel<<<(N + 255) / 256, 256>>>(cnt, N);
        count_kernel<<<(E + 255) / 256, 256>>>(rows, cnt, E);
        deg_reduce<<<nb, 256>>>(cnt, bsum, N);
        scan_bsums<<<1, 256>>>(bsum, nb);
        scan_apply<<<nb, 256>>>(cnt, bsum, off, cur, N, E);
        scatter_kernel<<<(E + 255) / 256, 256>>>(rows, cols, vals, cur, scols, svals, E);
        // SpMM1 + bias + relu -> h [N, HID]
        spmm_kernel<HID, true><<<(N + 7) / 8, 256>>>(off, scols, svals, xw, b1,
                                                     h, HID, nullptr, 0, N);
        // GEMM2: hw = h @ w2  [N, EMB]
        {
            dim3 grid((N + BM - 1) / BM, EMB / BN);
            sgemm_kernel<false><<<grid, 256>>>(h, w2, nullptr, hw, N, HID, EMB);
        }
        // SpMM2 + bias -> z_v, dual-write
        spmm_kernel<EMB, false><<<(N + 7) / 8, 256>>>(off, scols, svals, hw, b2,
                                                      out + (size_t)v * N * EMB, EMB,
                                                      zcat + (size_t)v * EMB, 3 * EMB, N);
    }

    const float* fw = (const float*)d_in[IFW];
    const float* fb = (const float*)d_in[IFB];
    const float* cl = (const float*)d_in[ICL];
    float* zf = out + (size_t)3 * N * EMB;
    float* qp = out + (size_t)4 * N * EMB;

    {
        dim3 grid((N + BM - 1) / BM, EMB / BN);
        sgemm_kernel<true><<<grid, 256>>>(zcat, fw, fb, zf, N, 3 * EMB, EMB);
    }
    q_kernel<<<(N + 255) / 256, 256>>>(zf, cl, qp, N);
}

// round 16
// speedup vs baseline: 1.1845x; 1.0364x over previous
#include <cuda_runtime.h>
#include <cuda_bf16.h>
#include <cstdint>

#define NNODES 50000
#define NV 3
#define NT3 (NNODES * NV)
#define MAXEDGES 800000
#define ME3 (MAXEDGES * NV)
#define HID 128
#define EMB 64
#define KCLUS 10
#define KPADMAX 1024

// ---------------- scratch (device globals; no allocation allowed) ----------------
__device__ float g_xw  [NV * NNODES * HID];     // per-view x @ w1
__device__ float g_h   [NV * NNODES * HID];     // per-view hidden
__device__ float g_hw  [NV * NNODES * EMB];     // per-view h @ w2
__device__ float g_zcat[NNODES * 3 * EMB];
__device__ int   g_cnt [NT3];
__device__ int   g_off [NT3 + 1];
__device__ int   g_cur [NT3];
__device__ int   g_scols[ME3];
__device__ float g_svals[ME3];
__device__ int   g_bsum[256];
__device__ __nv_bfloat16 g_xhi [NNODES * KPADMAX];
__device__ __nv_bfloat16 g_xlo [NNODES * KPADMAX];
__device__ __nv_bfloat16 g_wThi[HID * KPADMAX];
__device__ __nv_bfloat16 g_wTlo[HID * KPADMAX];

// =================================================================================
// fp32 -> bf16 hi/lo split conversion
// =================================================================================
__global__ void __launch_bounds__(256)
convx_kernel(const float* __restrict__ x, __nv_bfloat16* __restrict__ hi,
             __nv_bfloat16* __restrict__ lo, int Mrows, int din, int Kpad)
{
    int idx = blockIdx.x * blockDim.x + threadIdx.x;
    int half = Kpad >> 1;
    if (idx >= Mrows * half) return;
    int row = idx / half;
    int c   = (idx - row * half) * 2;

    float v0 = (c     < din) ? x[(size_t)row * din + c]     : 0.f;
    float v1 = (c + 1 < din) ? x[(size_t)row * din + c + 1] : 0.f;
    __nv_bfloat16 h0 = __float2bfloat16(v0);
    __nv_bfloat16 h1 = __float2bfloat16(v1);
    __nv_bfloat16 l0 = __float2bfloat16(v0 - __bfloat162float(h0));
    __nv_bfloat16 l1 = __float2bfloat16(v1 - __bfloat162float(h1));
    size_t o = (size_t)row * KPADMAX + c;
    *(__nv_bfloat162*)(hi + o) = __nv_bfloat162(h0, h1);
    *(__nv_bfloat162*)(lo + o) = __nv_bfloat162(l0, l1);
}

__global__ void __launch_bounds__(256)
convw_kernel(const float* __restrict__ w1, __nv_bfloat16* __restrict__ hiT,
             __nv_bfloat16* __restrict__ loT, int din, int Kpad)
{
    int idx = blockIdx.x * blockDim.x + threadIdx.x;
    if (idx >= HID * Kpad) return;
    int n = idx / Kpad;
    int k = idx - n * Kpad;
    float v = (k < din) ? w1[(size_t)k * HID + n] : 0.f;
    __nv_bfloat16 h = __float2bfloat16(v);
    __nv_bfloat16 l = __float2bfloat16(v - __bfloat162float(h));
    hiT[(size_t)n * KPADMAX + k] = h;
    loT[(size_t)n * KPADMAX + k] = l;
}

// =================================================================================
// GEMM1 (R12 proven): mma.sync m16n8k16 bf16 split hi/lo, ldmatrix fragments,
// cp.async 2-stage pipeline, K-chunk 16. CTA tile 128x64; 8 warps wm(2) x wn(4).
// =================================================================================
#define SMROW 48
#define OFF_AH 0
#define OFF_AL 6144
#define OFF_BH 12288
#define OFF_BL 15360
#define STAGE_BYTES 18432

static __device__ __forceinline__ uint32_t smem_u32(const void* p) {
    uint32_t a;
    asm("{ .reg .u64 t; cvta.to.shared.u64 t, %1; cvt.u32.u64 %0, t; }" : "=r"(a) : "l"(p));
    return a;
}

#define CPASYNC16(dst, src, sz) \
    asm volatile("cp.async.ca.shared.global [%0], [%1], 16, %2;" \
                 :: "r"(dst), "l"(src), "r"(sz))
#define CP_COMMIT() asm volatile("cp.async.commit_group;" ::: "memory")
#define CP_WAIT0()  asm volatile("cp.async.wait_group 0;" ::: "memory")
#define CP_WAIT1()  asm volatile("cp.async.wait_group 1;" ::: "memory")

#define LDSM4(r0, r1, r2, r3, addr) \
    asm volatile("ldmatrix.sync.aligned.m8n8.x4.shared.b16 {%0,%1,%2,%3}, [%4];" \
                 : "=r"(r0), "=r"(r1), "=r"(r2), "=r"(r3) : "r"(addr))

#define MMA16816(c, a0, a1, a2, a3, b0, b1)                                   \
    asm volatile(                                                             \
        "mma.sync.aligned.m16n8k16.row.col.f32.bf16.bf16.f32 "                \
        "{%0,%1,%2,%3}, {%4,%5,%6,%7}, {%8,%9}, {%0,%1,%2,%3};"               \
        : "+f"((c)[0]), "+f"((c)[1]), "+f"((c)[2]), "+f"((c)[3])              \
        : "r"(a0), "r"(a1), "r"(a2), "r"(a3), "r"(b0), "r"(b1))

__global__ void __launch_bounds__(256)
gemm1_mma(const __nv_bfloat16* __restrict__ Ahi, const __nv_bfloat16* __restrict__ Alo,
          const __nv_bfloat16* __restrict__ Bhi, const __nv_bfloat16* __restrict__ Blo,
          float* __restrict__ C, int M, int nChunk)
{
    __shared__ __align__(16) uint8_t sm[2][STAGE_BYTES];

    const int tid  = threadIdx.x;
    const int lane = tid & 31;
    const int wid  = tid >> 5;
    const int wm   = wid >> 2;
    const int wn   = wid & 3;
    const int g    = lane >> 2;
    const int t    = lane & 3;
    const int bm   = blockIdx.x * 128;
    const int bn   = blockIdx.y * 64;

    const uint32_t smb = smem_u32(sm);

    float acc[4][2][4];
    #pragma unroll
    for (int i = 0; i < 4; i++)
        #pragma unroll
        for (int j = 0; j < 2; j++)
            #pragma unroll
            for (int r = 0; r < 4; r++) acc[i][j][r] = 0.f;

    const int arow = tid >> 1;
    const int ac16 = tid & 1;
    const int bi   = tid & 127;
    const int brow = bi >> 1;
    const int bc16 = bi & 1;
    const bool doBlo = tid >= 128;
    const __nv_bfloat16* BsrcBase = doBlo ? Blo : Bhi;
    const uint32_t bDstOff = doBlo ? OFF_BL : OFF_BH;

    const int aGr    = bm + arow;
    const bool aOk   = aGr < M;
    const uint32_t aSz = aOk ? 16u : 0u;
    const size_t aRowOff = (size_t)(aOk ? aGr : 0) * KPADMAX + ac16 * 8;
    const size_t bRowOff = (size_t)(bn + brow) * KPADMAX + bc16 * 8;

    auto copyStage = [&](int stg, int ch) {
        const uint32_t sb = smb + stg * STAGE_BYTES;
        const int gk = ch * 16;
        CPASYNC16(sb + OFF_AH + arow * SMROW + ac16 * 16, Ahi + aRowOff + gk, aSz);
        CPASYNC16(sb + OFF_AL + arow * SMROW + ac16 * 16, Alo + aRowOff + gk, aSz);
        CPASYNC16(sb + bDstOff + brow * SMROW + bc16 * 16, BsrcBase + bRowOff + gk, 16u);
    };

    const int lrow = (lane < 16) ? lane : lane - 16;
    const uint32_t lcol = (lane < 16) ? 0 : 16;
    const uint32_t bAddrOff = (uint32_t)(wn * 16 + lrow) * SMROW + lcol;
    const uint32_t aAddrOff = (uint32_t)(wm * 64 + lrow) * SMROW + lcol;

    copyStage(0, 0);
    CP_COMMIT();

    for (int ch = 0; ch < nChunk; ch++) {
        if (ch + 1 < nChunk) {
            copyStage((ch + 1) & 1, ch + 1);
            CP_COMMIT();
            CP_WAIT1();
        } else {
            CP_WAIT0();
        }
        __syncthreads();

        const uint32_t sb = smb + (ch & 1) * STAGE_BYTES;

        uint32_t bh0, bh1, bh2, bh3, bl0, bl1, bl2, bl3;
        LDSM4(bh0, bh1, bh2, bh3, sb + OFF_BH + bAddrOff);
        LDSM4(bl0, bl1, bl2, bl3, sb + OFF_BL + bAddrOff);

        #pragma unroll
        for (int ma = 0; ma < 4; ma++) {
            uint32_t ah0, ah1, ah2, ah3, al0, al1, al2, al3;
            const uint32_t ao = aAddrOff + (uint32_t)(ma * 16) * SMROW;
            LDSM4(ah0, ah1, ah2, ah3, sb + OFF_AH + ao);
            LDSM4(al0, al1, al2, al3, sb + OFF_AL + ao);
            MMA16816(acc[ma][0], ah0, ah1, ah2, ah3, bh0, bh2);
            MMA16816(acc[ma][0], ah0, ah1, ah2, ah3, bl0, bl2);
            MMA16816(acc[ma][0], al0, al1, al2, al3, bh0, bh2);
            MMA16816(acc[ma][1], ah0, ah1, ah2, ah3, bh1, bh3);
            MMA16816(acc[ma][1], ah0, ah1, ah2, ah3, bl1, bl3);
            MMA16816(acc[ma][1], al0, al1, al2, al3, bh1, bh3);
        }
        __syncthreads();
    }

    #pragma unroll
    for (int ma = 0; ma < 4; ma++) {
        int r0 = bm + wm * 64 + ma * 16 + g;
        int r1 = r0 + 8;
        #pragma unroll
        for (int na = 0; na < 2; na++) {
            int cc = bn + wn * 16 + na * 8 + 2 * t;
            if (r0 < M)
                *(float2*)&C[(size_t)r0 * HID + cc] = make_float2(acc[ma][na][0], acc[ma][na][1]);
            if (r1 < M)
                *(float2*)&C[(size_t)r1 * HID + cc] = make_float2(acc[ma][na][2], acc[ma][na][3]);
        }
    }
}

// ---------------- tiled fp32 SGEMM (round-5 proven version) ---------------------
#define BM 128
#define BN 64
#define BK 8
#define TM 8
#define TN 4

template<bool EPI_BIAS_RELU>
__global__ void __launch_bounds__(256)
sgemm_kernel(const float* __restrict__ A, const float* __restrict__ B,
             const float* __restrict__ bias, float* __restrict__ C,
             int M, int K, int nc)
{
    __shared__ float As[BK][BM];
    __shared__ float Bs[BK][BN];

    const int tid = threadIdx.x;
    const int bm  = blockIdx.x * BM;
    const int bn  = blockIdx.y * BN;
    const int tx  = tid & 15;
    const int ty  = tid >> 4;

    float acc[TM][TN];
    #pragma unroll
    for (int i = 0; i < TM; i++)
        #pragma unroll
        for (int j = 0; j < TN; j++) acc[i][j] = 0.f;

    const int arow = tid >> 1;
    const int acol = (tid & 1) * 4;
    const int brow = tid >> 5;
    const int bcol = (tid & 31) * 2;

    const bool avalid = (bm + arow) < M;
    const float* Abase = A + (size_t)(bm + arow) * K + acol;
    const float* Bbase = B + (size_t)brow * nc + bn + bcol;

    for (int k0 = 0; k0 < K; k0 += BK) {
        float4 av = make_float4(0.f, 0.f, 0.f, 0.f);
        if (avalid) av = *(const float4*)(Abase + k0);
        As[acol + 0][arow] = av.x;
        As[acol + 1][arow] = av.y;
        As[acol + 2][arow] = av.z;
        As[acol + 3][arow] = av.w;

        float2 bv = *(const float2*)(Bbase + (size_t)k0 * nc);
        Bs[brow][bcol]     = bv.x;
        Bs[brow][bcol + 1] = bv.y;
        __syncthreads();

        #pragma unroll
        for (int kk = 0; kk < BK; kk++) {
            float4 a0 = *(const float4*)&As[kk][ty * TM];
            float4 a1 = *(const float4*)&As[kk][ty * TM + 4];
            float4 b0 = *(const float4*)&Bs[kk][tx * TN];
            float a[TM] = {a0.x, a0.y, a0.z, a0.w, a1.x, a1.y, a1.z, a1.w};
            float b[TN] = {b0.x, b0.y, b0.z, b0.w};
            #pragma unroll
            for (int i = 0; i < TM; i++)
                #pragma unroll
                for (int j = 0; j < TN; j++)
                    acc[i][j] = fmaf(a[i], b[j], acc[i][j]);
        }
        __syncthreads();
    }

    float bv[TN] = {0.f, 0.f, 0.f, 0.f};
    if (EPI_BIAS_RELU) {
        #pragma unroll
        for (int j = 0; j < TN; j++) bv[j] = bias[bn + tx * TN + j];
    }

    #pragma unroll
    for (int i = 0; i < TM; i++) {
        int r = bm + ty * TM + i;
        if (r < M) {
            float4 o;
            float v0 = acc[i][0], v1 = acc[i][1], v2 = acc[i][2], v3 = acc[i][3];
            if (EPI_BIAS_RELU) {
                v0 = fmaxf(v0 + bv[0], 0.f);
                v1 = fmaxf(v1 + bv[1], 0.f);
                v2 = fmaxf(v2 + bv[2], 0.f);
                v3 = fmaxf(v3 + bv[3], 0.f);
            }
            o.x = v0; o.y = v1; o.z = v2; o.w = v3;
            *(float4*)(C + (size_t)r * nc + bn + tx * TN) = o;
        }
    }
}

// =================================================================================
// Batched CSR construction across 3 views
// =================================================================================
struct Edges3 {
    const int *r0, *r1, *r2;     // rows per view
    const int *c0, *c1, *c2;     // cols per view
    const float *v0, *v1, *v2;   // vals per view
    int e1, e2, e3;              // prefix ends: e1=E0, e2=E0+E1, e3=total
};

__global__ void zero_kernel(int* p, int n)
{
    int i = blockIdx.x * blockDim.x + threadIdx.x;
    if (i < n) p[i] = 0;
}

__global__ void count3_kernel(Edges3 es, int* __restrict__ cnt)
{
    int i = blockIdx.x * blockDim.x + threadIdx.x;
    if (i >= es.e3) return;
    int v, el;
    const int* rp;
    if (i < es.e1)      { v = 0; el = i;         rp = es.r0; }
    else if (i < es.e2) { v = 1; el = i - es.e1; rp = es.r1; }
    else                { v = 2; el = i - es.e2; rp = es.r2; }
    atomicAdd(&cnt[v * NNODES + rp[el]], 1);
}

__global__ void __launch_bounds__(256)
deg_reduce(const int* __restrict__ cnt, int* __restrict__ bsum, int n)
{
    __shared__ int sh[256];
    int t = threadIdx.x;
    int base = blockIdx.x * 1024 + t * 4;
    int s = 0;
    if (base + 3 < n) {
        int4 v = *(const int4*)(cnt + base);
        s = v.x + v.y + v.z + v.w;
    } else {
        for (int i = 0; i < 4; i++) if (base + i < n) s += cnt[base + i];
    }
    sh[t] = s;
    __syncthreads();
    for (int d = 128; d > 0; d >>= 1) {
        if (t < d) sh[t] += sh[t + d];
        __syncthreads();
    }
    if (t == 0) bsum[blockIdx.x] = sh[0];
}

__global__ void __launch_bounds__(256)
scan_bsums(int* bsum, int nb)
{
    __shared__ int sh[256];
    int t = threadIdx.x;
    int v = (t < nb) ? bsum[t] : 0;
    sh[t] = v;
    __syncthreads();
    for (int d = 1; d < 256; d <<= 1) {
        int u = (t >= d) ? sh[t - d] : 0;
        __syncthreads();
        sh[t] += u;
        __syncthreads();
    }
    if (t < nb) bsum[t] = sh[t] - v;
}

__global__ void __launch_bounds__(256)
scan_apply(const int* __restrict__ cnt, const int* __restrict__ bsum,
           int* __restrict__ off, int* __restrict__ cur, int n, int E)
{
    __shared__ int sh[256];
    int t = threadIdx.x;
    int base = blockIdx.x * 1024 + t * 4;
    int c[4];
    int s = 0;
    #pragma unroll
    for (int i = 0; i < 4; i++) {
        c[i] = (base + i < n) ? cnt[base + i] : 0;
        s += c[i];
    }
    sh[t] = s;
    __syncthreads();
    for (int d = 1; d < 256; d <<= 1) {
        int u = (t >= d) ? sh[t - d] : 0;
        __syncthreads();
        sh[t] += u;
        __syncthreads();
    }
    int pre = bsum[blockIdx.x] + sh[t] - s;
    #pragma unroll
    for (int i = 0; i < 4; i++) {
        if (base + i < n) {
            off[base + i] = pre;
            cur[base + i] = pre;
            pre += c[i];
        }
    }
    if (blockIdx.x == 0 && t == 0) off[n] = E;
}

__global__ void scatter3_kernel(Edges3 es, int* __restrict__ cur,
                                int* __restrict__ scols, float* __restrict__ svals)
{
    int i = blockIdx.x * blockDim.x + threadIdx.x;
    if (i >= es.e3) return;
    int v, el;
    const int *rp, *cp;
    const float* vp;
    if (i < es.e1)      { v = 0; el = i;         rp = es.r0; cp = es.c0; vp = es.v0; }
    else if (i < es.e2) { v = 1; el = i - es.e1; rp = es.r1; cp = es.c1; vp = es.v1; }
    else                { v = 2; el = i - es.e2; rp = es.r2; cp = es.c2; vp = es.v2; }
    int p = atomicAdd(&cur[v * NNODES + rp[el]], 1);
    scols[p] = cp[el];
    svals[p] = vp[el];
}

// =================================================================================
// Batched row-per-warp SpMM across 3 views (global CSR offsets, concatenated
// scols/svals). dense/out strides = NNODES*NC per view.
// =================================================================================
struct Bias3 { const float *b0, *b1, *b2; };

template<int NC, bool RELU, bool ZCAT>
__global__ void __launch_bounds__(256)
spmm3_kernel(const int* __restrict__ off, const int* __restrict__ scols,
             const float* __restrict__ svals, const float* __restrict__ denseBase,
             Bias3 bias, float* __restrict__ outBase, float* __restrict__ zcat, int n)
{
    const int w    = (blockIdx.x * blockDim.x + threadIdx.x) >> 5;
    const int lane = threadIdx.x & 31;
    if (w >= n) return;
    const int v = w / NNODES;
    const int r = w - v * NNODES;

    const float* dense = denseBase + (size_t)v * NNODES * NC;
    const float* bp = (v == 0) ? bias.b0 : (v == 1) ? bias.b1 : bias.b2;

    const int s = off[w];
    const int e = off[w + 1];
    constexpr int V = NC / 32;
    const int c = lane * V;

    float acc[V];
    #pragma unroll
    for (int i = 0; i < V; i++) acc[i] = 0.f;

    int j = s;
    for (; j + 3 < e; j += 4) {
        int   ci[4];
        float vi[4];
        #pragma unroll
        for (int u = 0; u < 4; u++) { ci[u] = scols[j + u]; vi[u] = svals[j + u]; }
        if (V == 4) {
            float4 x[4];
            #pragma unroll
            for (int u = 0; u < 4; u++)
                x[u] = *(const float4*)(dense + (size_t)ci[u] * NC + c);
            #pragma unroll
            for (int u = 0; u < 4; u++) {
                acc[0] = fmaf(vi[u], x[u].x, acc[0]); acc[1] = fmaf(vi[u], x[u].y, acc[1]);
                acc[2] = fmaf(vi[u], x[u].z, acc[2]); acc[3] = fmaf(vi[u], x[u].w, acc[3]);
            }
        } else {
            float2 x[4];
            #pragma unroll
            for (int u = 0; u < 4; u++)
                x[u] = *(const float2*)(dense + (size_t)ci[u] * NC + c);
            #pragma unroll
            for (int u = 0; u < 4; u++) {
                acc[0] = fmaf(vi[u], x[u].x, acc[0]); acc[1] = fmaf(vi[u], x[u].y, acc[1]);
            }
        }
    }
    for (; j < e; j++) {
        const int   cc = scols[j];
        const float vv = svals[j];
        const float* dr = dense + (size_t)cc * NC + c;
        if (V == 4) {
            float4 x = *(const float4*)dr;
            acc[0] = fmaf(vv, x.x, acc[0]); acc[1] = fmaf(vv, x.y, acc[1]);
            acc[2] = fmaf(vv, x.z, acc[2]); acc[3] = fmaf(vv, x.w, acc[3]);
        } else {
            float2 x = *(const float2*)dr;
            acc[0] = fmaf(vv, x.x, acc[0]); acc[1] = fmaf(vv, x.y, acc[1]);
        }
    }

    float rr[V];
    #pragma unroll
    for (int i = 0; i < V; i++) {
        rr[i] = acc[i] + bp[c + i];
        if (RELU) rr[i] = fmaxf(rr[i], 0.f);
    }
    float* outp = outBase + (size_t)v * NNODES * NC + (size_t)r * NC + c;
    if (V == 4) {
        *(float4*)outp = make_float4(rr[0], rr[1], rr[2], rr[3]);
    } else {
        *(float2*)outp = make_float2(rr[0], rr[1]);
        if (ZCAT)
            *(float2*)(zcat + (size_t)r * (3 * EMB) + v * EMB + c) = make_float2(rr[0], rr[1]);
    }
}

// ---------------- DEC soft assignment q ----------------
__global__ void __launch_bounds__(256)
q_kernel(const float* __restrict__ zf, const float* __restrict__ cluster,
         float* __restrict__ q, int n)
{
    __shared__ float cs[KCLUS * EMB];
    for (int i = threadIdx.x; i < KCLUS * EMB; i += blockDim.x) cs[i] = cluster[i];
    __syncthreads();

    int nid = blockIdx.x * blockDim.x + threadIdx.x;
    if (nid >= n) return;

    float z[EMB];
    const float* zr = zf + (size_t)nid * EMB;
    #pragma unroll
    for (int i = 0; i < EMB; i++) z[i] = zr[i];

    float qq[KCLUS];
    float s = 0.f;
    #pragma unroll
    for (int k = 0; k < KCLUS; k++) {
        float d = 0.f;
        #pragma unroll
        for (int i = 0; i < EMB; i++) {
            float diff = z[i] - cs[k * EMB + i];
            d = fmaf(diff, diff, d);
        }
        qq[k] = 1.f / (1.f + d);
        s += qq[k];
    }
    float inv = 1.f / s;
    #pragma unroll
    for (int k = 0; k < KCLUS; k++)
        q[(size_t)nid * KCLUS + k] = qq[k] * inv;
}

// ---------------- host launcher ----------------
extern "C" void kernel_launch(void* const* d_in, const int* in_sizes, int n_in,
                              void* d_out, int out_size)
{
    float *xw, *h, *hw, *zcat, *svals;
    int *cnt, *off, *cur, *scols, *bsum;
    void *xhi, *xlo, *wThi, *wTlo;
    cudaGetSymbolAddress((void**)&xw,    g_xw);
    cudaGetSymbolAddress((void**)&h,     g_h);
    cudaGetSymbolAddress((void**)&hw,    g_hw);
    cudaGetSymbolAddress((void**)&zcat,  g_zcat);
    cudaGetSymbolAddress((void**)&cnt,   g_cnt);
    cudaGetSymbolAddress((void**)&off,   g_off);
    cudaGetSymbolAddress((void**)&cur,   g_cur);
    cudaGetSymbolAddress((void**)&scols, g_scols);
    cudaGetSymbolAddress((void**)&svals, g_svals);
    cudaGetSymbolAddress((void**)&bsum,  g_bsum);
    cudaGetSymbolAddress(&xhi,  g_xhi);
    cudaGetSymbolAddress(&xlo,  g_xlo);
    cudaGetSymbolAddress(&wThi, g_wThi);
    cudaGetSymbolAddress(&wTlo, g_wTlo);

    float* out = (float*)d_out;
    const int N = NNODES;

    int IX[3], IR[3], IC[3], IV[3], IW1[3], IB1[3], IW2[3], IB2[3], IFW, IFB, ICL;
    bool dictOrder = (n_in >= 3) && (in_sizes[1] == in_sizes[2]) && (in_sizes[1] < in_sizes[0]);
    if (dictOrder) {
        for (int v = 0; v < 3; v++) {
            IX[v] = 8 * v + 0; IR[v] = 8 * v + 1; IC[v] = 8 * v + 2; IV[v] = 8 * v + 3;
            IW1[v] = 8 * v + 4; IB1[v] = 8 * v + 5; IW2[v] = 8 * v + 6; IB2[v] = 8 * v + 7;
        }
        IFW = 24; IFB = 25; ICL = 26;
    } else {
        for (int v = 0; v < 3; v++) {
            IX[v] = v;
            IR[v] = 3 + 3 * v; IC[v] = 4 + 3 * v; IV[v] = 5 + 3 * v;
            IW1[v] = 12 + 4 * v; IB1[v] = 13 + 4 * v; IW2[v] = 14 + 4 * v; IB2[v] = 15 + 4 * v;
        }
        IFW = 24; IFB = 25; ICL = 26;
    }

    // ---- Phase 1: per-view conversion + tensor GEMM1 (reuses single xhi/xlo) ----
    for (int v = 0; v < 3; v++) {
        const float* x  = (const float*)d_in[IX[v]];
        const float* w1 = (const float*)d_in[IW1[v]];
        const int din   = in_sizes[IX[v]] / N;
        const int Kpad  = ((din + 63) / 64) * 64;
        const int nChunk = Kpad / 16;

        int total = N * (Kpad / 2);
        convx_kernel<<<(total + 255) / 256, 256>>>(x, (__nv_bfloat16*)xhi,
                                                   (__nv_bfloat16*)xlo, N, din, Kpad);
        int wt = HID * Kpad;
        convw_kernel<<<(wt + 255) / 256, 256>>>(w1, (__nv_bfloat16*)wThi,
                                                (__nv_bfloat16*)wTlo, din, Kpad);
        dim3 grid((N + 127) / 128, HID / 64);
        gemm1_mma<<<grid, 256>>>((const __nv_bfloat16*)xhi, (const __nv_bfloat16*)xlo,
                                 (const __nv_bfloat16*)wThi, (const __nv_bfloat16*)wTlo,
                                 xw + (size_t)v * N * HID, N, nChunk);
    }

    // ---- Phase 2: batched CSR build ----
    Edges3 es;
    es.r0 = (const int*)d_in[IR[0]]; es.r1 = (const int*)d_in[IR[1]]; es.r2 = (const int*)d_in[IR[2]];
    es.c0 = (const int*)d_in[IC[0]]; es.c1 = (const int*)d_in[IC[1]]; es.c2 = (const int*)d_in[IC[2]];
    es.v0 = (const float*)d_in[IV[0]]; es.v1 = (const float*)d_in[IV[1]]; es.v2 = (const float*)d_in[IV[2]];
    const int E0 = in_sizes[IR[0]], E1 = in_sizes[IR[1]], E2 = in_sizes[IR[2]];
    es.e1 = E0; es.e2 = E0 + E1; es.e3 = E0 + E1 + E2;
    const int n3 = 3 * N;
    const int nb3 = (n3 + 1023) / 1024;

    zero_kernel<<<(n3 + 255) / 256, 256>>>(cnt, n3);
    count3_kernel<<<(es.e3 + 255) / 256, 256>>>(es, cnt);
    deg_reduce<<<nb3, 256>>>(cnt, bsum, n3);
    scan_bsums<<<1, 256>>>(bsum, nb3);
    scan_apply<<<nb3, 256>>>(cnt, bsum, off, cur, n3, es.e3);
    scatter3_kernel<<<(es.e3 + 255) / 256, 256>>>(es, cur, scols, svals);

    // ---- Phase 3: batched SpMM1 -> h ----
    Bias3 b1s = { (const float*)d_in[IB1[0]], (const float*)d_in[IB1[1]], (const float*)d_in[IB1[2]] };
    spmm3_kernel<HID, true, false><<<(n3 + 7) / 8, 256>>>(off, scols, svals, xw, b1s,
                                                          h, nullptr, n3);

    // ---- Phase 4: per-view GEMM2 -> hw ----
    for (int v = 0; v < 3; v++) {
        const float* w2 = (const float*)d_in[IW2[v]];
        dim3 grid((N + BM - 1) / BM, EMB / BN);
        sgemm_kernel<false><<<grid, 256>>>(h + (size_t)v * N * HID, w2, nullptr,
                                           hw + (size_t)v * N * EMB, N, HID, EMB);
    }

    // ---- Phase 5: batched SpMM2 -> z (d_out) + zcat ----
    Bias3 b2s = { (const float*)d_in[IB2[0]], (const float*)d_in[IB2[1]], (const float*)d_in[IB2[2]] };
    spmm3_kernel<EMB, false, true><<<(n3 + 7) / 8, 256>>>(off, scols, svals, hw, b2s,
                                                          out, zcat, n3);

    // ---- Phase 6: fusion + q ----
    const float* fw = (const float*)d_in[IFW];
    const float* fb = (const float*)d_in[IFB];
    const float* cl = (const float*)d_in[ICL];
    float* zf = out + (size_t)3 * N * EMB;
    float* qp = out + (size_t)4 * N * EMB;

    {
        dim3 grid((N + BM - 1) / BM, EMB / BN);
        sgemm_kernel<true><<<grid, 256>>>(zcat, fw, fb, zf, N, 3 * EMB, EMB);
    }
    q_kernel<<<(N + 255) / 256, 256>>>(zf, cl, qp, N);
}

// round 17
// speedup vs baseline: 1.2826x; 1.0828x over previous
#include <cuda_runtime.h>
#include <cuda_bf16.h>
#include <cstdint>

#define NNODES 50000
#define NV 3
#define NT3 (NNODES * NV)
#define MAXEDGES 800000
#define ME3 (MAXEDGES * NV)
#define HID 128
#define EMB 64
#define KCLUS 10
#define KPADMAX 1024

// ---------------- scratch (device globals; no allocation allowed) ----------------
__device__ float g_xw  [NV * NNODES * HID];     // per-view x @ w1
__device__ float g_h   [NV * NNODES * HID];     // per-view hidden
__device__ float g_hw  [NV * NNODES * EMB];     // per-view h @ w2
__device__ float g_zcat[NNODES * 3 * EMB];
__device__ int   g_cnt [NT3];
__device__ int   g_off [NT3 + 1];
__device__ int   g_cur [NT3];
__device__ int   g_scols[ME3];
__device__ float g_svals[ME3];
__device__ int   g_bsum[256];
__device__ __nv_bfloat16 g_xhi [NNODES * KPADMAX];
__device__ __nv_bfloat16 g_xlo [NNODES * KPADMAX];
__device__ __nv_bfloat16 g_wThi[HID * KPADMAX];
__device__ __nv_bfloat16 g_wTlo[HID * KPADMAX];

// =================================================================================
// fp32 -> bf16 hi/lo split conversion, vectorized: 8 cols/thread, 128-bit LDG/STG.
// Requires din % 8 == 0 (holds for 1000/800/600); padding region writes zeros.
// =================================================================================
__global__ void __launch_bounds__(256)
convx_kernel(const float* __restrict__ x, __nv_bfloat16* __restrict__ hi,
             __nv_bfloat16* __restrict__ lo, int Mrows, int din, int Kpad)
{
    int idx = blockIdx.x * blockDim.x + threadIdx.x;
    int chunks = Kpad >> 3;                 // 8-col chunks per row
    if (idx >= Mrows * chunks) return;
    int row = idx / chunks;
    int c   = (idx - row * chunks) * 8;

    float f[8];
    if (c + 8 <= din) {
        float4 a = *(const float4*)(x + (size_t)row * din + c);
        float4 b = *(const float4*)(x + (size_t)row * din + c + 4);
        f[0] = a.x; f[1] = a.y; f[2] = a.z; f[3] = a.w;
        f[4] = b.x; f[5] = b.y; f[6] = b.z; f[7] = b.w;
    } else {
        #pragma unroll
        for (int i = 0; i < 8; i++) f[i] = 0.f;
    }

    uint32_t hp[4], lp[4];
    #pragma unroll
    for (int i = 0; i < 4; i++) {
        __nv_bfloat16 h0 = __float2bfloat16(f[2 * i]);
        __nv_bfloat16 h1 = __float2bfloat16(f[2 * i + 1]);
        __nv_bfloat16 l0 = __float2bfloat16(f[2 * i]     - __bfloat162float(h0));
        __nv_bfloat16 l1 = __float2bfloat16(f[2 * i + 1] - __bfloat162float(h1));
        __nv_bfloat162 hpair(h0, h1), lpair(l0, l1);
        hp[i] = *(const uint32_t*)&hpair;
        lp[i] = *(const uint32_t*)&lpair;
    }
    size_t o = (size_t)row * KPADMAX + c;
    *(uint4*)(hi + o) = make_uint4(hp[0], hp[1], hp[2], hp[3]);
    *(uint4*)(lo + o) = make_uint4(lp[0], lp[1], lp[2], lp[3]);
}

__global__ void __launch_bounds__(256)
convw_kernel(const float* __restrict__ w1, __nv_bfloat16* __restrict__ hiT,
             __nv_bfloat16* __restrict__ loT, int din, int Kpad)
{
    int idx = blockIdx.x * blockDim.x + threadIdx.x;
    if (idx >= HID * Kpad) return;
    int n = idx / Kpad;
    int k = idx - n * Kpad;
    float v = (k < din) ? w1[(size_t)k * HID + n] : 0.f;
    __nv_bfloat16 h = __float2bfloat16(v);
    __nv_bfloat16 l = __float2bfloat16(v - __bfloat162float(h));
    hiT[(size_t)n * KPADMAX + k] = h;
    loT[(size_t)n * KPADMAX + k] = l;
}

// =================================================================================
// GEMM1 (R12 proven): mma.sync m16n8k16 bf16 split hi/lo, ldmatrix fragments,
// cp.async 2-stage pipeline, K-chunk 16. CTA tile 128x64; 8 warps wm(2) x wn(4).
// =================================================================================
#define SMROW 48
#define OFF_AH 0
#define OFF_AL 6144
#define OFF_BH 12288
#define OFF_BL 15360
#define STAGE_BYTES 18432

static __device__ __forceinline__ uint32_t smem_u32(const void* p) {
    uint32_t a;
    asm("{ .reg .u64 t; cvta.to.shared.u64 t, %1; cvt.u32.u64 %0, t; }" : "=r"(a) : "l"(p));
    return a;
}

#define CPASYNC16(dst, src, sz) \
    asm volatile("cp.async.ca.shared.global [%0], [%1], 16, %2;" \
                 :: "r"(dst), "l"(src), "r"(sz))
#define CP_COMMIT() asm volatile("cp.async.commit_group;" ::: "memory")
#define CP_WAIT0()  asm volatile("cp.async.wait_group 0;" ::: "memory")
#define CP_WAIT1()  asm volatile("cp.async.wait_group 1;" ::: "memory")

#define LDSM4(r0, r1, r2, r3, addr) \
    asm volatile("ldmatrix.sync.aligned.m8n8.x4.shared.b16 {%0,%1,%2,%3}, [%4];" \
                 : "=r"(r0), "=r"(r1), "=r"(r2), "=r"(r3) : "r"(addr))

#define MMA16816(c, a0, a1, a2, a3, b0, b1)                                   \
    asm volatile(                                                             \
        "mma.sync.aligned.m16n8k16.row.col.f32.bf16.bf16.f32 "                \
        "{%0,%1,%2,%3}, {%4,%5,%6,%7}, {%8,%9}, {%0,%1,%2,%3};"               \
        : "+f"((c)[0]), "+f"((c)[1]), "+f"((c)[2]), "+f"((c)[3])              \
        : "r"(a0), "r"(a1), "r"(a2), "r"(a3), "r"(b0), "r"(b1))

__global__ void __launch_bounds__(256)
gemm1_mma(const __nv_bfloat16* __restrict__ Ahi, const __nv_bfloat16* __restrict__ Alo,
          const __nv_bfloat16* __restrict__ Bhi, const __nv_bfloat16* __restrict__ Blo,
          float* __restrict__ C, int M, int nChunk)
{
    __shared__ __align__(16) uint8_t sm[2][STAGE_BYTES];

    const int tid  = threadIdx.x;
    const int lane = tid & 31;
    const int wid  = tid >> 5;
    const int wm   = wid >> 2;
    const int wn   = wid & 3;
    const int g    = lane >> 2;
    const int t    = lane & 3;
    const int bm   = blockIdx.x * 128;
    const int bn   = blockIdx.y * 64;

    const uint32_t smb = smem_u32(sm);

    float acc[4][2][4];
    #pragma unroll
    for (int i = 0; i < 4; i++)
        #pragma unroll
        for (int j = 0; j < 2; j++)
            #pragma unroll
            for (int r = 0; r < 4; r++) acc[i][j][r] = 0.f;

    const int arow = tid >> 1;
    const int ac16 = tid & 1;
    const int bi   = tid & 127;
    const int brow = bi >> 1;
    const int bc16 = bi & 1;
    const bool doBlo = tid >= 128;
    const __nv_bfloat16* BsrcBase = doBlo ? Blo : Bhi;
    const uint32_t bDstOff = doBlo ? OFF_BL : OFF_BH;

    const int aGr    = bm + arow;
    const bool aOk   = aGr < M;
    const uint32_t aSz = aOk ? 16u : 0u;
    const size_t aRowOff = (size_t)(aOk ? aGr : 0) * KPADMAX + ac16 * 8;
    const size_t bRowOff = (size_t)(bn + brow) * KPADMAX + bc16 * 8;

    auto copyStage = [&](int stg, int ch) {
        const uint32_t sb = smb + stg * STAGE_BYTES;
        const int gk = ch * 16;
        CPASYNC16(sb + OFF_AH + arow * SMROW + ac16 * 16, Ahi + aRowOff + gk, aSz);
        CPASYNC16(sb + OFF_AL + arow * SMROW + ac16 * 16, Alo + aRowOff + gk, aSz);
        CPASYNC16(sb + bDstOff + brow * SMROW + bc16 * 16, BsrcBase + bRowOff + gk, 16u);
    };

    const int lrow = (lane < 16) ? lane : lane - 16;
    const uint32_t lcol = (lane < 16) ? 0 : 16;
    const uint32_t bAddrOff = (uint32_t)(wn * 16 + lrow) * SMROW + lcol;
    const uint32_t aAddrOff = (uint32_t)(wm * 64 + lrow) * SMROW + lcol;

    copyStage(0, 0);
    CP_COMMIT();

    for (int ch = 0; ch < nChunk; ch++) {
        if (ch + 1 < nChunk) {
            copyStage((ch + 1) & 1, ch + 1);
            CP_COMMIT();
            CP_WAIT1();
        } else {
            CP_WAIT0();
        }
        __syncthreads();

        const uint32_t sb = smb + (ch & 1) * STAGE_BYTES;

        uint32_t bh0, bh1, bh2, bh3, bl0, bl1, bl2, bl3;
        LDSM4(bh0, bh1, bh2, bh3, sb + OFF_BH + bAddrOff);
        LDSM4(bl0, bl1, bl2, bl3, sb + OFF_BL + bAddrOff);

        #pragma unroll
        for (int ma = 0; ma < 4; ma++) {
            uint32_t ah0, ah1, ah2, ah3, al0, al1, al2, al3;
            const uint32_t ao = aAddrOff + (uint32_t)(ma * 16) * SMROW;
            LDSM4(ah0, ah1, ah2, ah3, sb + OFF_AH + ao);
            LDSM4(al0, al1, al2, al3, sb + OFF_AL + ao);
            MMA16816(acc[ma][0], ah0, ah1, ah2, ah3, bh0, bh2);
            MMA16816(acc[ma][0], ah0, ah1, ah2, ah3, bl0, bl2);
            MMA16816(acc[ma][0], al0, al1, al2, al3, bh0, bh2);
            MMA16816(acc[ma][1], ah0, ah1, ah2, ah3, bh1, bh3);
            MMA16816(acc[ma][1], ah0, ah1, ah2, ah3, bl1, bl3);
            MMA16816(acc[ma][1], al0, al1, al2, al3, bh1, bh3);
        }
        __syncthreads();
    }

    #pragma unroll
    for (int ma = 0; ma < 4; ma++) {
        int r0 = bm + wm * 64 + ma * 16 + g;
        int r1 = r0 + 8;
        #pragma unroll
        for (int na = 0; na < 2; na++) {
            int cc = bn + wn * 16 + na * 8 + 2 * t;
            if (r0 < M)
                *(float2*)&C[(size_t)r0 * HID + cc] = make_float2(acc[ma][na][0], acc[ma][na][1]);
            if (r1 < M)
                *(float2*)&C[(size_t)r1 * HID + cc] = make_float2(acc[ma][na][2], acc[ma][na][3]);
        }
    }
}

// ---------------- tiled fp32 SGEMM (round-5 proven version) ---------------------
#define BM 128
#define BN 64
#define BK 8
#define TM 8
#define TN 4

template<bool EPI_BIAS_RELU>
__global__ void __launch_bounds__(256)
sgemm_kernel(const float* __restrict__ A, const float* __restrict__ B,
             const float* __restrict__ bias, float* __restrict__ C,
             int M, int K, int nc)
{
    __shared__ float As[BK][BM];
    __shared__ float Bs[BK][BN];

    const int tid = threadIdx.x;
    const int bm  = blockIdx.x * BM;
    const int bn  = blockIdx.y * BN;
    const int tx  = tid & 15;
    const int ty  = tid >> 4;

    float acc[TM][TN];
    #pragma unroll
    for (int i = 0; i < TM; i++)
        #pragma unroll
        for (int j = 0; j < TN; j++) acc[i][j] = 0.f;

    const int arow = tid >> 1;
    const int acol = (tid & 1) * 4;
    const int brow = tid >> 5;
    const int bcol = (tid & 31) * 2;

    const bool avalid = (bm + arow) < M;
    const float* Abase = A + (size_t)(bm + arow) * K + acol;
    const float* Bbase = B + (size_t)brow * nc + bn + bcol;

    for (int k0 = 0; k0 < K; k0 += BK) {
        float4 av = make_float4(0.f, 0.f, 0.f, 0.f);
        if (avalid) av = *(const float4*)(Abase + k0);
        As[acol + 0][arow] = av.x;
        As[acol + 1][arow] = av.y;
        As[acol + 2][arow] = av.z;
        As[acol + 3][arow] = av.w;

        float2 bv = *(const float2*)(Bbase + (size_t)k0 * nc);
        Bs[brow][bcol]     = bv.x;
        Bs[brow][bcol + 1] = bv.y;
        __syncthreads();

        #pragma unroll
        for (int kk = 0; kk < BK; kk++) {
            float4 a0 = *(const float4*)&As[kk][ty * TM];
            float4 a1 = *(const float4*)&As[kk][ty * TM + 4];
            float4 b0 = *(const float4*)&Bs[kk][tx * TN];
            float a[TM] = {a0.x, a0.y, a0.z, a0.w, a1.x, a1.y, a1.z, a1.w};
            float b[TN] = {b0.x, b0.y, b0.z, b0.w};
            #pragma unroll
            for (int i = 0; i < TM; i++)
                #pragma unroll
                for (int j = 0; j < TN; j++)
                    acc[i][j] = fmaf(a[i], b[j], acc[i][j]);
        }
        __syncthreads();
    }

    float bv[TN] = {0.f, 0.f, 0.f, 0.f};
    if (EPI_BIAS_RELU) {
        #pragma unroll
        for (int j = 0; j < TN; j++) bv[j] = bias[bn + tx * TN + j];
    }

    #pragma unroll
    for (int i = 0; i < TM; i++) {
        int r = bm + ty * TM + i;
        if (r < M) {
            float4 o;
            float v0 = acc[i][0], v1 = acc[i][1], v2 = acc[i][2], v3 = acc[i][3];
            if (EPI_BIAS_RELU) {
                v0 = fmaxf(v0 + bv[0], 0.f);
                v1 = fmaxf(v1 + bv[1], 0.f);
                v2 = fmaxf(v2 + bv[2], 0.f);
                v3 = fmaxf(v3 + bv[3], 0.f);
            }
            o.x = v0; o.y = v1; o.z = v2; o.w = v3;
            *(float4*)(C + (size_t)r * nc + bn + tx * TN) = o;
        }
    }
}

// =================================================================================
// Batched CSR construction across 3 views
// =================================================================================
struct Edges3 {
    const int *r0, *r1, *r2;
    const int *c0, *c1, *c2;
    const float *v0, *v1, *v2;
    int e1, e2, e3;
};

__global__ void zero_kernel(int* p, int n)
{
    int i = blockIdx.x * blockDim.x + threadIdx.x;
    if (i < n) p[i] = 0;
}

__global__ void count3_kernel(Edges3 es, int* __restrict__ cnt)
{
    int i = blockIdx.x * blockDim.x + threadIdx.x;
    if (i >= es.e3) return;
    int v, el;
    const int* rp;
    if (i < es.e1)      { v = 0; el = i;         rp = es.r0; }
    else if (i < es.e2) { v = 1; el = i - es.e1; rp = es.r1; }
    else                { v = 2; el = i - es.e2; rp = es.r2; }
    atomicAdd(&cnt[v * NNODES + rp[el]], 1);
}

__global__ void __launch_bounds__(256)
deg_reduce(const int* __restrict__ cnt, int* __restrict__ bsum, int n)
{
    __shared__ int sh[256];
    int t = threadIdx.x;
    int base = blockIdx.x * 1024 + t * 4;
    int s = 0;
    if (base + 3 < n) {
        int4 v = *(const int4*)(cnt + base);
        s = v.x + v.y + v.z + v.w;
    } else {
        for (int i = 0; i < 4; i++) if (base + i < n) s += cnt[base + i];
    }
    sh[t] = s;
    __syncthreads();
    for (int d = 128; d > 0; d >>= 1) {
        if (t < d) sh[t] += sh[t + d];
        __syncthreads();
    }
    if (t == 0) bsum[blockIdx.x] = sh[0];
}

__global__ void __launch_bounds__(256)
scan_bsums(int* bsum, int nb)
{
    __shared__ int sh[256];
    int t = threadIdx.x;
    int v = (t < nb) ? bsum[t] : 0;
    sh[t] = v;
    __syncthreads();
    for (int d = 1; d < 256; d <<= 1) {
        int u = (t >= d) ? sh[t - d] : 0;
        __syncthreads();
        sh[t] += u;
        __syncthreads();
    }
    if (t < nb) bsum[t] = sh[t] - v;
}

__global__ void __launch_bounds__(256)
scan_apply(const int* __restrict__ cnt, const int* __restrict__ bsum,
           int* __restrict__ off, int* __restrict__ cur, int n, int E)
{
    __shared__ int sh[256];
    int t = threadIdx.x;
    int base = blockIdx.x * 1024 + t * 4;
    int c[4];
    int s = 0;
    #pragma unroll
    for (int i = 0; i < 4; i++) {
        c[i] = (base + i < n) ? cnt[base + i] : 0;
        s += c[i];
    }
    sh[t] = s;
    __syncthreads();
    for (int d = 1; d < 256; d <<= 1) {
        int u = (t >= d) ? sh[t - d] : 0;
        __syncthreads();
        sh[t] += u;
        __syncthreads();
    }
    int pre = bsum[blockIdx.x] + sh[t] - s;
    #pragma unroll
    for (int i = 0; i < 4; i++) {
        if (base + i < n) {
            off[base + i] = pre;
            cur[base + i] = pre;
            pre += c[i];
        }
    }
    if (blockIdx.x == 0 && t == 0) off[n] = E;
}

__global__ void scatter3_kernel(Edges3 es, int* __restrict__ cur,
                                int* __restrict__ scols, float* __restrict__ svals)
{
    int i = blockIdx.x * blockDim.x + threadIdx.x;
    if (i >= es.e3) return;
    int v, el;
    const int *rp, *cp;
    const float* vp;
    if (i < es.e1)      { v = 0; el = i;         rp = es.r0; cp = es.c0; vp = es.v0; }
    else if (i < es.e2) { v = 1; el = i - es.e1; rp = es.r1; cp = es.c1; vp = es.v1; }
    else                { v = 2; el = i - es.e2; rp = es.r2; cp = es.c2; vp = es.v2; }
    int p = atomicAdd(&cur[v * NNODES + rp[el]], 1);
    scols[p] = cp[el];
    svals[p] = vp[el];
}

// =================================================================================
// Batched row-per-warp SpMM across 3 views
// =================================================================================
struct Bias3 { const float *b0, *b1, *b2; };

template<int NC, bool RELU, bool ZCAT>
__global__ void __launch_bounds__(256)
spmm3_kernel(const int* __restrict__ off, const int* __restrict__ scols,
             const float* __restrict__ svals, const float* __restrict__ denseBase,
             Bias3 bias, float* __restrict__ outBase, float* __restrict__ zcat, int n)
{
    const int w    = (blockIdx.x * blockDim.x + threadIdx.x) >> 5;
    const int lane = threadIdx.x & 31;
    if (w >= n) return;
    const int v = w / NNODES;
    const int r = w - v * NNODES;

    const float* dense = denseBase + (size_t)v * NNODES * NC;
    const float* bp = (v == 0) ? bias.b0 : (v == 1) ? bias.b1 : bias.b2;

    const int s = off[w];
    const int e = off[w + 1];
    constexpr int V = NC / 32;
    const int c = lane * V;

    float acc[V];
    #pragma unroll
    for (int i = 0; i < V; i++) acc[i] = 0.f;

    int j = s;
    for (; j + 3 < e; j += 4) {
        int   ci[4];
        float vi[4];
        #pragma unroll
        for (int u = 0; u < 4; u++) { ci[u] = scols[j + u]; vi[u] = svals[j + u]; }
        if (V == 4) {
            float4 x[4];
            #pragma unroll
            for (int u = 0; u < 4; u++)
                x[u] = *(const float4*)(dense + (size_t)ci[u] * NC + c);
            #pragma unroll
            for (int u = 0; u < 4; u++) {
                acc[0] = fmaf(vi[u], x[u].x, acc[0]); acc[1] = fmaf(vi[u], x[u].y, acc[1]);
                acc[2] = fmaf(vi[u], x[u].z, acc[2]); acc[3] = fmaf(vi[u], x[u].w, acc[3]);
            }
        } else {
            float2 x[4];
            #pragma unroll
            for (int u = 0; u < 4; u++)
                x[u] = *(const float2*)(dense + (size_t)ci[u] * NC + c);
            #pragma unroll
            for (int u = 0; u < 4; u++) {
                acc[0] = fmaf(vi[u], x[u].x, acc[0]); acc[1] = fmaf(vi[u], x[u].y, acc[1]);
            }
        }
    }
    for (; j < e; j++) {
        const int   cc = scols[j];
        const float vv = svals[j];
        const float* dr = dense + (size_t)cc * NC + c;
        if (V == 4) {
            float4 x = *(const float4*)dr;
            acc[0] = fmaf(vv, x.x, acc[0]); acc[1] = fmaf(vv, x.y, acc[1]);
            acc[2] = fmaf(vv, x.z, acc[2]); acc[3] = fmaf(vv, x.w, acc[3]);
        } else {
            float2 x = *(const float2*)dr;
            acc[0] = fmaf(vv, x.x, acc[0]); acc[1] = fmaf(vv, x.y, acc[1]);
        }
    }

    float rr[V];
    #pragma unroll
    for (int i = 0; i < V; i++) {
        rr[i] = acc[i] + bp[c + i];
        if (RELU) rr[i] = fmaxf(rr[i], 0.f);
    }
    float* outp = outBase + (size_t)v * NNODES * NC + (size_t)r * NC + c;
    if (V == 4) {
        *(float4*)outp = make_float4(rr[0], rr[1], rr[2], rr[3]);
    } else {
        *(float2*)outp = make_float2(rr[0], rr[1]);
        if (ZCAT)
            *(float2*)(zcat + (size_t)r * (3 * EMB) + v * EMB + c) = make_float2(rr[0], rr[1]);
    }
}

// ---------------- DEC soft assignment q ----------------
__global__ void __launch_bounds__(256)
q_kernel(const float* __restrict__ zf, const float* __restrict__ cluster,
         float* __restrict__ q, int n)
{
    __shared__ float cs[KCLUS * EMB];
    for (int i = threadIdx.x; i < KCLUS * EMB; i += blockDim.x) cs[i] = cluster[i];
    __syncthreads();

    int nid = blockIdx.x * blockDim.x + threadIdx.x;
    if (nid >= n) return;

    float z[EMB];
    const float* zr = zf + (size_t)nid * EMB;
    #pragma unroll
    for (int i = 0; i < EMB; i++) z[i] = zr[i];

    float qq[KCLUS];
    float s = 0.f;
    #pragma unroll
    for (int k = 0; k < KCLUS; k++) {
        float d = 0.f;
        #pragma unroll
        for (int i = 0; i < EMB; i++) {
            float diff = z[i] - cs[k * EMB + i];
            d = fmaf(diff, diff, d);
        }
        qq[k] = 1.f / (1.f + d);
        s += qq[k];
    }
    float inv = 1.f / s;
    #pragma unroll
    for (int k = 0; k < KCLUS; k++)
        q[(size_t)nid * KCLUS + k] = qq[k] * inv;
}

// ---------------- host launcher ----------------
extern "C" void kernel_launch(void* const* d_in, const int* in_sizes, int n_in,
                              void* d_out, int out_size)
{
    float *xw, *h, *hw, *zcat, *svals;
    int *cnt, *off, *cur, *scols, *bsum;
    void *xhi, *xlo, *wThi, *wTlo;
    cudaGetSymbolAddress((void**)&xw,    g_xw);
    cudaGetSymbolAddress((void**)&h,     g_h);
    cudaGetSymbolAddress((void**)&hw,    g_hw);
    cudaGetSymbolAddress((void**)&zcat,  g_zcat);
    cudaGetSymbolAddress((void**)&cnt,   g_cnt);
    cudaGetSymbolAddress((void**)&off,   g_off);
    cudaGetSymbolAddress((void**)&cur,   g_cur);
    cudaGetSymbolAddress((void**)&scols, g_scols);
    cudaGetSymbolAddress((void**)&svals, g_svals);
    cudaGetSymbolAddress((void**)&bsum,  g_bsum);
    cudaGetSymbolAddress(&xhi,  g_xhi);
    cudaGetSymbolAddress(&xlo,  g_xlo);
    cudaGetSymbolAddress(&wThi, g_wThi);
    cudaGetSymbolAddress(&wTlo, g_wTlo);

    float* out = (float*)d_out;
    const int N = NNODES;

    int IX[3], IR[3], IC[3], IV[3], IW1[3], IB1[3], IW2[3], IB2[3], IFW, IFB, ICL;
    bool dictOrder = (n_in >= 3) && (in_sizes[1] == in_sizes[2]) && (in_sizes[1] < in_sizes[0]);
    if (dictOrder) {
        for (int v = 0; v < 3; v++) {
            IX[v] = 8 * v + 0; IR[v] = 8 * v + 1; IC[v] = 8 * v + 2; IV[v] = 8 * v + 3;
            IW1[v] = 8 * v + 4; IB1[v] = 8 * v + 5; IW2[v] = 8 * v + 6; IB2[v] = 8 * v + 7;
        }
        IFW = 24; IFB = 25; ICL = 26;
    } else {
        for (int v = 0; v < 3; v++) {
            IX[v] = v;
            IR[v] = 3 + 3 * v; IC[v] = 4 + 3 * v; IV[v] = 5 + 3 * v;
            IW1[v] = 12 + 4 * v; IB1[v] = 13 + 4 * v; IW2[v] = 14 + 4 * v; IB2[v] = 15 + 4 * v;
        }
        IFW = 24; IFB = 25; ICL = 26;
    }

    // ---- Phase 1: per-view conversion + tensor GEMM1 ----
    for (int v = 0; v < 3; v++) {
        const float* x  = (const float*)d_in[IX[v]];
        const float* w1 = (const float*)d_in[IW1[v]];
        const int din   = in_sizes[IX[v]] / N;
        const int Kpad  = ((din + 63) / 64) * 64;
        const int nChunk = Kpad / 16;

        int total = N * (Kpad / 8);
        convx_kernel<<<(total + 255) / 256, 256>>>(x, (__nv_bfloat16*)xhi,
                                                   (__nv_bfloat16*)xlo, N, din, Kpad);
        int wt = HID * Kpad;
        convw_kernel<<<(wt + 255) / 256, 256>>>(w1, (__nv_bfloat16*)wThi,
                                                (__nv_bfloat16*)wTlo, din, Kpad);
        dim3 grid((N + 127) / 128, HID / 64);
        gemm1_mma<<<grid, 256>>>((const __nv_bfloat16*)xhi, (const __nv_bfloat16*)xlo,
                                 (const __nv_bfloat16*)wThi, (const __nv_bfloat16*)wTlo,
                                 xw + (size_t)v * N * HID, N, nChunk);
    }

    // ---- Phase 2: batched CSR build ----
    Edges3 es;
    es.r0 = (const int*)d_in[IR[0]]; es.r1 = (const int*)d_in[IR[1]]; es.r2 = (const int*)d_in[IR[2]];
    es.c0 = (const int*)d_in[IC[0]]; es.c1 = (const int*)d_in[IC[1]]; es.c2 = (const int*)d_in[IC[2]];
    es.v0 = (const float*)d_in[IV[0]]; es.v1 = (const float*)d_in[IV[1]]; es.v2 = (const float*)d_in[IV[2]];
    const int E0 = in_sizes[IR[0]], E1 = in_sizes[IR[1]], E2 = in_sizes[IR[2]];
    es.e1 = E0; es.e2 = E0 + E1; es.e3 = E0 + E1 + E2;
    const int n3 = 3 * N;
    const int nb3 = (n3 + 1023) / 1024;

    zero_kernel<<<(n3 + 255) / 256, 256>>>(cnt, n3);
    count3_kernel<<<(es.e3 + 255) / 256, 256>>>(es, cnt);
    deg_reduce<<<nb3, 256>>>(cnt, bsum, n3);
    scan_bsums<<<1, 256>>>(bsum, nb3);
    scan_apply<<<nb3, 256>>>(cnt, bsum, off, cur, n3, es.e3);
    scatter3_kernel<<<(es.e3 + 255) / 256, 256>>>(es, cur, scols, svals);

    // ---- Phase 3: batched SpMM1 -> h ----
    Bias3 b1s = { (const float*)d_in[IB1[0]], (const float*)d_in[IB1[1]], (const float*)d_in[IB1[2]] };
    spmm3_kernel<HID, true, false><<<(n3 + 7) / 8, 256>>>(off, scols, svals, xw, b1s,
                                                          h, nullptr, n3);

    // ---- Phase 4: per-view GEMM2 -> hw ----
    for (int v = 0; v < 3; v++) {
        const float* w2 = (const float*)d_in[IW2[v]];
        dim3 grid((N + BM - 1) / BM, EMB / BN);
        sgemm_kernel<false><<<grid, 256>>>(h + (size_t)v * N * HID, w2, nullptr,
                                           hw + (size_t)v * N * EMB, N, HID, EMB);
    }

    // ---- Phase 5: batched SpMM2 -> z (d_out) + zcat ----
    Bias3 b2s = { (const float*)d_in[IB2[0]], (const float*)d_in[IB2[1]], (const float*)d_in[IB2[2]] };
    spmm3_kernel<EMB, false, true><<<(n3 + 7) / 8, 256>>>(off, scols, svals, hw, b2s,
                                                          out, zcat, n3);

    // ---- Phase 6: fusion + q ----
    const float* fw = (const float*)d_in[IFW];
    const float* fb = (const float*)d_in[IFB];
    const float* cl = (const float*)d_in[ICL];
    float* zf = out + (size_t)3 * N * EMB;
    float* qp = out + (size_t)4 * N * EMB;

    {
        dim3 grid((N + BM - 1) / BM, EMB / BN);
        sgemm_kernel<true><<<grid, 256>>>(zcat, fw, fb, zf, N, 3 * EMB, EMB);
    }
    q_kernel<<<(N + 255) / 256, 256>>>(zf, cl, qp, N);
}